// round 5
// baseline (speedup 1.0000x reference)
#include <cuda_runtime.h>
#include <cstdint>

#define Dd 768
#define Cc 256
#define BLn 1024

// Scratch (device globals: allocation-free rule)
__device__ float g_Htmp[BLn * Dd];
__device__ float g_Hs[BLn * Dd];
__device__ float g_He[BLn * Dd];
__device__ float g_Ls[BLn * Cc];
__device__ float g_Le[BLn * Cc];
__device__ float g_T[(size_t)BLn * Cc * Dd];     // T[bi][c][e]
__device__ float g_W1t[(size_t)Cc * Dd * Dd];    // W1t[c][e][d]
__device__ float g_Xr[BLn * Dd];
__device__ float g_w1r[Dd * Dd];
__device__ float g_w2r[Dd * Dd];
__device__ float g_w3r[Dd * Dd];
__device__ float g_w4r[Dd * Dd];
__device__ float g_W2r[Cc * 2 * Dd];

static __device__ __forceinline__ float rna(float x) {
    uint32_t u;
    asm("cvt.rna.tf32.f32 %0, %1;" : "=r"(u) : "f"(x));
    return __uint_as_float(u);
}
static __device__ __forceinline__ uint32_t smem_u32(const void* p) {
    uint32_t a;
    asm("{ .reg .u64 t; cvta.to.shared.u64 t, %1; cvt.u32.u64 %0, t; }" : "=r"(a) : "l"(p));
    return a;
}
static __device__ __forceinline__ void cp16(uint32_t dst, const float* src) {
    asm volatile("cp.async.cg.shared.global [%0], [%1], 16;" :: "r"(dst), "l"(src) : "memory");
}
static __device__ __forceinline__ void cp_commit() {
    asm volatile("cp.async.commit_group;" ::: "memory");
}
template <int N>
static __device__ __forceinline__ void cp_wait() {
    asm volatile("cp.async.wait_group %0;" :: "n"(N) : "memory");
}
static __device__ __forceinline__ void mma_tf32(float& c0, float& c1, float& c2, float& c3,
                                                uint32_t a0, uint32_t a1, uint32_t a2, uint32_t a3,
                                                uint32_t b0, uint32_t b1) {
    asm volatile(
        "mma.sync.aligned.m16n8k8.row.col.f32.tf32.tf32.f32 "
        "{%0,%1,%2,%3}, {%4,%5,%6,%7}, {%8,%9}, {%0,%1,%2,%3};"
        : "+f"(c0), "+f"(c1), "+f"(c2), "+f"(c3)
        : "r"(a0), "r"(a1), "r"(a2), "r"(a3), "r"(b0), "r"(b1));
}

// ---------------------------------------------------------------------------
// tf32 mma.sync GEMM: C[z][m,n] = sum_k A[z][m,k] * B[z][n,k], K=768.
// CTA tile 128x256, BK=32, 8 warps (2x4) of 64x64 each, 3-stage cp.async.
// modes: 0 plain | 1 rna(relu(+b1)) | 2 rna(+b1) | 3 rna | 4 biaffine epilogue
// ---------------------------------------------------------------------------
#define PADK 36
#define ASTG (128 * PADK)              // A floats per stage
#define BSTG (256 * PADK)              // B floats per stage
#define SMEM_BYTES (3 * (ASTG + BSTG) * 4)   // 165888

__global__ void __launch_bounds__(256, 1)
gemm_tc(const float* A, long saz, int lda,
        const float* B, long sbz, int ldb,
        float* C, long scz, long ldc,
        int mode, const float* __restrict__ b1,
        const float* __restrict__ Lsg, const float* __restrict__ Leg,
        const float* __restrict__ W2bg, const float* __restrict__ biasg)
{
    extern __shared__ float smem[];
    float* As = smem;                  // [3][128][36]
    float* Bs = smem + 3 * ASTG;       // [3][256][36]
    const uint32_t sbase = smem_u32(smem);
    const uint32_t bbase = sbase + 3 * ASTG * 4;

    const int tid = threadIdx.x;
    const int z = blockIdx.z;
    if (mode == 4) {
        A += (long)(z >> 9) * 512 * Dd;
        B += (long)z * Cc * Dd;
        C += (long)z * 512 * Cc;
    } else {
        A += z * saz; B += z * sbz; C += z * scz;
    }
    const int m0 = blockIdx.y * 128, n0 = blockIdx.x * 256;

    // producer mapping: A 4 chunks (128 rows x 8 quads), B 8 chunks (256 rows)
    const int pr = tid >> 3, pc = tid & 7;
    const float* pa0 = A + (long)(m0 + pr) * lda + pc * 4;
    const float* pb0 = B + (long)(n0 + pr) * ldb + pc * 4;
    const uint32_t qoff = (uint32_t)(pr * PADK + pc * 4) * 4;
    const uint32_t qa0 = sbase + qoff;
    const uint32_t qb0 = bbase + qoff;

    float acc[4][8][4];
#pragma unroll
    for (int mi = 0; mi < 4; mi++)
#pragma unroll
        for (int ni = 0; ni < 8; ni++)
#pragma unroll
            for (int r = 0; r < 4; r++) acc[mi][ni][r] = 0.f;

    const int lane = tid & 31, w = tid >> 5;
    const int g = lane >> 2, tig = lane & 3;
    const int wm = w & 1, wn = w >> 1;           // warp tile: 64 (M) x 64 (N)

    // prologue: stages 0 and 1
#pragma unroll
    for (int s = 0; s < 2; s++) {
        const uint32_t ao = s * (ASTG * 4), bo = s * (BSTG * 4);
        const long go = (long)s * 32;
#pragma unroll
        for (int i = 0; i < 4; i++)
            cp16(qa0 + ao + i * (32 * PADK * 4), pa0 + (long)(32 * i) * lda + go);
#pragma unroll
        for (int i = 0; i < 8; i++)
            cp16(qb0 + bo + i * (32 * PADK * 4), pb0 + (long)(32 * i) * ldb + go);
        cp_commit();
    }

    for (int k0 = 0; k0 < 24; k0++) {
        if (k0 < 23) cp_wait<1>(); else cp_wait<0>();
        __syncthreads();
        if (k0 + 2 < 24) {
            const int s = (k0 + 2) % 3;
            const uint32_t ao = s * (ASTG * 4), bo = s * (BSTG * 4);
            const long go = (long)(k0 + 2) * 32;
#pragma unroll
            for (int i = 0; i < 4; i++)
                cp16(qa0 + ao + i * (32 * PADK * 4), pa0 + (long)(32 * i) * lda + go);
#pragma unroll
            for (int i = 0; i < 8; i++)
                cp16(qb0 + bo + i * (32 * PADK * 4), pb0 + (long)(32 * i) * ldb + go);
            cp_commit();
        }

        const int st = k0 % 3;
        const float* aw = As + st * ASTG + (wm * 64) * PADK;
        const float* bw = Bs + st * BSTG + (wn * 64) * PADK;

#pragma unroll
        for (int ks = 0; ks < 4; ks++) {
            const int kb = ks * 8 + tig;
            uint32_t af[4][4], bf[8][2];
#pragma unroll
            for (int mi = 0; mi < 4; mi++) {
                const float* p = aw + (mi * 16 + g) * PADK + kb;
                af[mi][0] = __float_as_uint(p[0]);
                af[mi][1] = __float_as_uint(p[8 * PADK]);
                af[mi][2] = __float_as_uint(p[4]);
                af[mi][3] = __float_as_uint(p[8 * PADK + 4]);
            }
#pragma unroll
            for (int ni = 0; ni < 8; ni++) {
                const float* p = bw + (ni * 8 + g) * PADK + kb;
                bf[ni][0] = __float_as_uint(p[0]);
                bf[ni][1] = __float_as_uint(p[4]);
            }
#pragma unroll
            for (int mi = 0; mi < 4; mi++)
#pragma unroll
                for (int ni = 0; ni < 8; ni++)
                    mma_tf32(acc[mi][ni][0], acc[mi][ni][1], acc[mi][ni][2], acc[mi][ni][3],
                             af[mi][0], af[mi][1], af[mi][2], af[mi][3],
                             bf[ni][0], bf[ni][1]);
        }
    }

    // epilogue
    const float* lsr = nullptr; const float* leb = nullptr;
    if (mode == 4) {
        lsr = Lsg + (long)z * Cc;
        leb = Leg + (long)(z >> 9) * 512 * Cc;
    }
#pragma unroll
    for (int mi = 0; mi < 4; mi++) {
#pragma unroll
        for (int ni = 0; ni < 8; ni++) {
            const int col = n0 + wn * 64 + ni * 8 + tig * 2;
#pragma unroll
            for (int h = 0; h < 2; h++) {
                const int row = m0 + wm * 64 + mi * 16 + g + h * 8;
                float x0 = acc[mi][ni][h * 2];
                float x1 = acc[mi][ni][h * 2 + 1];
                if (mode == 1) {
                    x0 = rna(fmaxf(x0 + b1[col], 0.f));
                    x1 = rna(fmaxf(x1 + b1[col + 1], 0.f));
                } else if (mode == 2) {
                    x0 = rna(x0 + b1[col]);
                    x1 = rna(x1 + b1[col + 1]);
                } else if (mode == 3) {
                    x0 = rna(x0); x1 = rna(x1);
                } else if (mode == 4) {
                    const float* ler = leb + (long)row * Cc;
                    x0 += lsr[col] + ler[col] + W2bg[col] + biasg[col];
                    x1 += lsr[col + 1] + ler[col + 1] + W2bg[col + 1] + biasg[col + 1];
                }
                *(float2*)(C + (long)row * ldc + col) = make_float2(x0, x1);
            }
        }
    }
}

// W1t[c][e][d] = rna(W1[c][d][e])
__global__ void __launch_bounds__(256)
transpose_k(const float* __restrict__ W1, float* __restrict__ W1t)
{
    __shared__ float ts[32][33];
    const int c = blockIdx.z;
    const float* src = W1 + (size_t)c * Dd * Dd;
    float* dst = W1t + (size_t)c * Dd * Dd;
    const int d0 = blockIdx.y * 32, e0 = blockIdx.x * 32;
    const int x = threadIdx.x, y = threadIdx.y;
#pragma unroll
    for (int j = 0; j < 32; j += 8)
        ts[y + j][x] = src[(size_t)(d0 + y + j) * Dd + e0 + x];
    __syncthreads();
#pragma unroll
    for (int j = 0; j < 32; j += 8)
        dst[(size_t)(e0 + y + j) * Dd + d0 + x] = rna(ts[x][y + j]);
}

__global__ void round_k(const float* __restrict__ x, float* __restrict__ y, int n)
{
    for (int i = blockIdx.x * blockDim.x + threadIdx.x; i < n; i += gridDim.x * blockDim.x)
        y[i] = rna(x[i]);
}

extern "C" void kernel_launch(void* const* d_in, const int* in_sizes, int n_in,
                              void* d_out, int out_size)
{
    const float* hidden = (const float*)d_in[0];
    const float* sw1 = (const float*)d_in[1];
    const float* sb1 = (const float*)d_in[2];
    const float* sw2 = (const float*)d_in[3];
    const float* sb2 = (const float*)d_in[4];
    const float* ew1 = (const float*)d_in[5];
    const float* eb1 = (const float*)d_in[6];
    const float* ew2 = (const float*)d_in[7];
    const float* eb2 = (const float*)d_in[8];
    const float* W1  = (const float*)d_in[9];
    const float* W2w = (const float*)d_in[10];
    const float* W2b = (const float*)d_in[11];
    const float* bs  = (const float*)d_in[12];
    float* out = (float*)d_out;

    static int smem_set = 0;
    if (!smem_set) {
        cudaFuncSetAttribute(gemm_tc, cudaFuncAttributeMaxDynamicSharedMemorySize, SMEM_BYTES);
        smem_set = 1;
    }

    float *Htmp, *Hs, *He, *Ls, *Le, *T, *W1t, *Xr, *w1r, *w2r, *w3r, *w4r, *W2r;
    cudaGetSymbolAddress((void**)&Htmp, g_Htmp);
    cudaGetSymbolAddress((void**)&Hs, g_Hs);
    cudaGetSymbolAddress((void**)&He, g_He);
    cudaGetSymbolAddress((void**)&Ls, g_Ls);
    cudaGetSymbolAddress((void**)&Le, g_Le);
    cudaGetSymbolAddress((void**)&T, g_T);
    cudaGetSymbolAddress((void**)&W1t, g_W1t);
    cudaGetSymbolAddress((void**)&Xr, g_Xr);
    cudaGetSymbolAddress((void**)&w1r, g_w1r);
    cudaGetSymbolAddress((void**)&w2r, g_w2r);
    cudaGetSymbolAddress((void**)&w3r, g_w3r);
    cudaGetSymbolAddress((void**)&w4r, g_w4r);
    cudaGetSymbolAddress((void**)&W2r, g_W2r);

    // tf32-round inputs and weights
    round_k<<<192, 256>>>(hidden, Xr, BLn * Dd);
    round_k<<<192, 256>>>(sw1, w1r, Dd * Dd);
    round_k<<<192, 256>>>(sw2, w2r, Dd * Dd);
    round_k<<<192, 256>>>(ew1, w3r, Dd * Dd);
    round_k<<<192, 256>>>(ew2, w4r, Dd * Dd);
    round_k<<<192, 256>>>(W2w, W2r, Cc * 2 * Dd);
    transpose_k<<<dim3(24, 24, Cc), dim3(32, 8)>>>(W1, W1t);

    const dim3 blk(256);
    // MLPs (M=1024, N=768, K=768)
    gemm_tc<<<dim3(3, 8, 1), blk, SMEM_BYTES>>>(Xr, 0, Dd, w1r, 0, Dd, Htmp, 0, Dd,
                                                1, sb1, nullptr, nullptr, nullptr, nullptr);
    gemm_tc<<<dim3(3, 8, 1), blk, SMEM_BYTES>>>(Htmp, 0, Dd, w2r, 0, Dd, Hs, 0, Dd,
                                                2, sb2, nullptr, nullptr, nullptr, nullptr);
    gemm_tc<<<dim3(3, 8, 1), blk, SMEM_BYTES>>>(Xr, 0, Dd, w3r, 0, Dd, Htmp, 0, Dd,
                                                1, eb1, nullptr, nullptr, nullptr, nullptr);
    gemm_tc<<<dim3(3, 8, 1), blk, SMEM_BYTES>>>(Htmp, 0, Dd, w4r, 0, Dd, He, 0, Dd,
                                                2, eb2, nullptr, nullptr, nullptr, nullptr);
    // Ls / Le (M=1024, N=256, K=768); W2r row stride 1536
    gemm_tc<<<dim3(1, 8, 1), blk, SMEM_BYTES>>>(Hs, 0, Dd, W2r, 0, 2 * Dd, Ls, 0, Cc,
                                                0, nullptr, nullptr, nullptr, nullptr, nullptr);
    gemm_tc<<<dim3(1, 8, 1), blk, SMEM_BYTES>>>(He, 0, Dd, W2r + Dd, 0, 2 * Dd, Le, 0, Cc,
                                                0, nullptr, nullptr, nullptr, nullptr, nullptr);
    // Phase A: T[bi, c, e] = sum_d Hs[bi,d] * W1t[c,e,d]   (z = c)
    gemm_tc<<<dim3(3, 8, Cc), blk, SMEM_BYTES>>>(Hs, 0, Dd,
                                                 W1t, (long)Dd * Dd, Dd,
                                                 T, (long)Dd, (long)Cc * Dd,
                                                 3, nullptr, nullptr, nullptr, nullptr, nullptr);
    // Phase B: out[z, j, c] = sum_e He_b[j,e] * T[z,c,e] + linear   (z = bi)
    gemm_tc<<<dim3(1, 4, BLn), blk, SMEM_BYTES>>>(He, 0, Dd, T, 0, Dd, out, 0, Cc,
                                                  4, nullptr, Ls, Le, W2b, bs);
}

// round 6
// speedup vs baseline: 1.8385x; 1.8385x over previous
#include <cuda_runtime.h>
#include <cuda_fp16.h>
#include <cstdint>

#define Dd 768
#define Cc 256
#define BLn 1024

// Scratch (device globals: allocation-free rule)
__device__ __half g_Xh[BLn * Dd];
__device__ __half g_w1h[Dd * Dd];
__device__ __half g_w2h[Dd * Dd];
__device__ __half g_w3h[Dd * Dd];
__device__ __half g_w4h[Dd * Dd];
__device__ __half g_W2h[Cc * 2 * Dd];
__device__ __half g_W1th[(size_t)Cc * Dd * Dd];   // [c][e][d] half
__device__ __half g_Htmph[BLn * Dd];
__device__ __half g_Hsh[BLn * Dd];
__device__ __half g_Heh[BLn * Dd];
__device__ __half g_Th[(size_t)BLn * Cc * Dd];    // T[bi][c][e] half
__device__ float  g_Ls[BLn * Cc];
__device__ float  g_Le[BLn * Cc];

static __device__ __forceinline__ uint32_t smem_u32(const void* p) {
    uint32_t a;
    asm("{ .reg .u64 t; cvta.to.shared.u64 t, %1; cvt.u32.u64 %0, t; }" : "=r"(a) : "l"(p));
    return a;
}
static __device__ __forceinline__ void cp16(uint32_t dst, const void* src) {
    asm volatile("cp.async.cg.shared.global [%0], [%1], 16;" :: "r"(dst), "l"(src) : "memory");
}
static __device__ __forceinline__ void cp_commit() {
    asm volatile("cp.async.commit_group;" ::: "memory");
}
template <int N>
static __device__ __forceinline__ void cp_wait() {
    asm volatile("cp.async.wait_group %0;" :: "n"(N) : "memory");
}
static __device__ __forceinline__ void mma_f16(float& c0, float& c1, float& c2, float& c3,
                                               uint32_t a0, uint32_t a1, uint32_t a2, uint32_t a3,
                                               uint32_t b0, uint32_t b1) {
    asm volatile(
        "mma.sync.aligned.m16n8k16.row.col.f32.f16.f16.f32 "
        "{%0,%1,%2,%3}, {%4,%5,%6,%7}, {%8,%9}, {%0,%1,%2,%3};"
        : "+f"(c0), "+f"(c1), "+f"(c2), "+f"(c3)
        : "r"(a0), "r"(a1), "r"(a2), "r"(a3), "r"(b0), "r"(b1));
}

// ---------------------------------------------------------------------------
// fp16 mma.sync GEMM: C[z][m,n] = sum_k A[z][m,k]*B[z][n,k], K=768, fp32 accum.
// CTA 128x128, BK=64 halves (12 iters), 8 warps (2x4) of 64x32, 2-stage.
// Smem rows: 72 halves (word stride 36 = 4 mod 32 -> conflict-free fragments).
// modes: 0 f32 out | 1 h out relu(+b1) | 2 h out +b1 | 3 h out | 4 f32 biaffine
// ---------------------------------------------------------------------------
#define ROWH 72
#define ASTG (128 * ROWH)                  // halves per stage per operand
#define SMEM_BYTES (4 * ASTG * 2 * 2 / 2)  // 2 stages * 2 ops * 128*72*2B = 73728

__global__ void __launch_bounds__(256, 2)
gemm_h(const __half* A, long saz, int lda,
       const __half* B, long sbz, int ldb,
       void* Cv, long scz, long ldc,
       int mode, const float* __restrict__ b1,
       const float* __restrict__ Lsg, const float* __restrict__ Leg,
       const float* __restrict__ W2bg, const float* __restrict__ biasg)
{
    extern __shared__ __half smh[];
    __half* As = smh;                      // [2][128][72]
    __half* Bs = smh + 2 * ASTG;
    const uint32_t sbase = smem_u32(smh);
    const uint32_t bbase = sbase + 2 * ASTG * 2;

    const int tid = threadIdx.x;
    const int z = blockIdx.z;
    float* Cf = (float*)Cv;
    __half* Ch = (__half*)Cv;
    if (mode == 4) {
        A += (long)(z >> 9) * 512 * Dd;
        B += (long)z * Cc * Dd;
        Cf += (long)z * 512 * Cc;
    } else {
        A += z * saz; B += z * sbz;
        Cf += z * scz; Ch += z * scz;
    }
    const int m0 = blockIdx.y * 128, n0 = blockIdx.x * 128;

    // producer: 128 rows x 8 chunks (16B = 8 halves) per operand, 4 chunks/thread
    const int pr = tid >> 3, pc = tid & 7;           // row 0..31 base pattern
    const __half* pa0 = A + (long)(m0 + pr) * lda + pc * 8;
    const __half* pb0 = B + (long)(n0 + pr) * ldb + pc * 8;
    const uint32_t qoff = (uint32_t)(pr * ROWH * 2 + pc * 16);
    const uint32_t qa0 = sbase + qoff;
    const uint32_t qb0 = bbase + qoff;
    const uint32_t stgb = ASTG * 2;

    float acc[4][4][4];
#pragma unroll
    for (int mi = 0; mi < 4; mi++)
#pragma unroll
        for (int ni = 0; ni < 4; ni++)
#pragma unroll
            for (int r = 0; r < 4; r++) acc[mi][ni][r] = 0.f;

    const int lane = tid & 31, w = tid >> 5;
    const int g = lane >> 2, tig = lane & 3;
    const int wm = w & 1, wn = w >> 1;               // warp tile 64(M) x 32(N)

    // prologue: stage 0  (rows pr, pr+32, pr+64, pr+96)
#pragma unroll
    for (int i = 0; i < 4; i++) {
        cp16(qa0 + i * (32 * ROWH * 2), pa0 + (long)(32 * i) * lda);
        cp16(qb0 + i * (32 * ROWH * 2), pb0 + (long)(32 * i) * ldb);
    }
    cp_commit();

    for (int k0 = 0; k0 < 12; k0++) {
        cp_wait<0>();
        __syncthreads();
        if (k0 + 1 < 12) {
            const uint32_t so = ((k0 + 1) & 1) * stgb;
            const long go = (long)(k0 + 1) * 64;
#pragma unroll
            for (int i = 0; i < 4; i++) {
                cp16(qa0 + so + i * (32 * ROWH * 2), pa0 + (long)(32 * i) * lda + go);
                cp16(qb0 + so + i * (32 * ROWH * 2), pb0 + (long)(32 * i) * ldb + go);
            }
            cp_commit();
        }

        const __half* aw = As + (k0 & 1) * ASTG + (wm * 64) * ROWH;
        const __half* bw = Bs + (k0 & 1) * ASTG + (wn * 32) * ROWH;

#pragma unroll
        for (int ks = 0; ks < 4; ks++) {
            const int kh = ks * 16 + 2 * tig;        // half offset in row
            uint32_t af[4][4], bf[4][2];
#pragma unroll
            for (int mi = 0; mi < 4; mi++) {
                const __half* p = aw + (mi * 16 + g) * ROWH + kh;
                af[mi][0] = *(const uint32_t*)(p);
                af[mi][1] = *(const uint32_t*)(p + 8 * ROWH);
                af[mi][2] = *(const uint32_t*)(p + 8);
                af[mi][3] = *(const uint32_t*)(p + 8 * ROWH + 8);
            }
#pragma unroll
            for (int ni = 0; ni < 4; ni++) {
                const __half* p = bw + (ni * 8 + g) * ROWH + kh;
                bf[ni][0] = *(const uint32_t*)(p);
                bf[ni][1] = *(const uint32_t*)(p + 8);
            }
#pragma unroll
            for (int mi = 0; mi < 4; mi++)
#pragma unroll
                for (int ni = 0; ni < 4; ni++)
                    mma_f16(acc[mi][ni][0], acc[mi][ni][1], acc[mi][ni][2], acc[mi][ni][3],
                            af[mi][0], af[mi][1], af[mi][2], af[mi][3],
                            bf[ni][0], bf[ni][1]);
        }
    }

    // epilogue
    const float* lsr = nullptr; const float* leb = nullptr;
    if (mode == 4) {
        lsr = Lsg + (long)z * Cc;
        leb = Leg + (long)(z >> 9) * 512 * Cc;
    }
#pragma unroll
    for (int mi = 0; mi < 4; mi++) {
#pragma unroll
        for (int ni = 0; ni < 4; ni++) {
            const int col = n0 + wn * 32 + ni * 8 + tig * 2;
#pragma unroll
            for (int h = 0; h < 2; h++) {
                const int row = m0 + wm * 64 + mi * 16 + g + h * 8;
                float x0 = acc[mi][ni][h * 2];
                float x1 = acc[mi][ni][h * 2 + 1];
                if (mode == 1) {
                    x0 = fmaxf(x0 + b1[col], 0.f);
                    x1 = fmaxf(x1 + b1[col + 1], 0.f);
                } else if (mode == 2) {
                    x0 += b1[col]; x1 += b1[col + 1];
                } else if (mode == 4) {
                    const float* ler = leb + (long)row * Cc;
                    x0 += lsr[col] + ler[col] + W2bg[col] + biasg[col];
                    x1 += lsr[col + 1] + ler[col + 1] + W2bg[col + 1] + biasg[col + 1];
                }
                if (mode == 0 || mode == 4) {
                    *(float2*)(Cf + (long)row * ldc + col) = make_float2(x0, x1);
                } else {
                    *(__half2*)(Ch + (long)row * ldc + col) = __floats2half2_rn(x0, x1);
                }
            }
        }
    }
}

// W1th[c][e][d] = half(W1[c][d][e])
__global__ void __launch_bounds__(256)
transpose_h(const float* __restrict__ W1, __half* __restrict__ W1t)
{
    __shared__ float ts[32][33];
    const int c = blockIdx.z;
    const float* src = W1 + (size_t)c * Dd * Dd;
    __half* dst = W1t + (size_t)c * Dd * Dd;
    const int d0 = blockIdx.y * 32, e0 = blockIdx.x * 32;
    const int x = threadIdx.x, y = threadIdx.y;
#pragma unroll
    for (int j = 0; j < 32; j += 8)
        ts[y + j][x] = src[(size_t)(d0 + y + j) * Dd + e0 + x];
    __syncthreads();
#pragma unroll
    for (int j = 0; j < 32; j += 8)
        dst[(size_t)(e0 + y + j) * Dd + d0 + x] = __float2half_rn(ts[x][y + j]);
}

__global__ void f2h_k(const float* __restrict__ x, __half* __restrict__ y, int n)
{
    for (int i = blockIdx.x * blockDim.x + threadIdx.x; i < n; i += gridDim.x * blockDim.x)
        y[i] = __float2half_rn(x[i]);
}

extern "C" void kernel_launch(void* const* d_in, const int* in_sizes, int n_in,
                              void* d_out, int out_size)
{
    const float* hidden = (const float*)d_in[0];
    const float* sw1 = (const float*)d_in[1];
    const float* sb1 = (const float*)d_in[2];
    const float* sw2 = (const float*)d_in[3];
    const float* sb2 = (const float*)d_in[4];
    const float* ew1 = (const float*)d_in[5];
    const float* eb1 = (const float*)d_in[6];
    const float* ew2 = (const float*)d_in[7];
    const float* eb2 = (const float*)d_in[8];
    const float* W1  = (const float*)d_in[9];
    const float* W2w = (const float*)d_in[10];
    const float* W2b = (const float*)d_in[11];
    const float* bs  = (const float*)d_in[12];
    float* out = (float*)d_out;

    static int smem_set = 0;
    if (!smem_set) {
        cudaFuncSetAttribute(gemm_h, cudaFuncAttributeMaxDynamicSharedMemorySize, SMEM_BYTES);
        smem_set = 1;
    }

    __half *Xh, *w1h, *w2h, *w3h, *w4h, *W2h, *W1th, *Htmph, *Hsh, *Heh, *Th;
    float *Ls, *Le;
    cudaGetSymbolAddress((void**)&Xh, g_Xh);
    cudaGetSymbolAddress((void**)&w1h, g_w1h);
    cudaGetSymbolAddress((void**)&w2h, g_w2h);
    cudaGetSymbolAddress((void**)&w3h, g_w3h);
    cudaGetSymbolAddress((void**)&w4h, g_w4h);
    cudaGetSymbolAddress((void**)&W2h, g_W2h);
    cudaGetSymbolAddress((void**)&W1th, g_W1th);
    cudaGetSymbolAddress((void**)&Htmph, g_Htmph);
    cudaGetSymbolAddress((void**)&Hsh, g_Hsh);
    cudaGetSymbolAddress((void**)&Heh, g_Heh);
    cudaGetSymbolAddress((void**)&Th, g_Th);
    cudaGetSymbolAddress((void**)&Ls, g_Ls);
    cudaGetSymbolAddress((void**)&Le, g_Le);

    // fp16 conversions
    f2h_k<<<192, 256>>>(hidden, Xh, BLn * Dd);
    f2h_k<<<192, 256>>>(sw1, w1h, Dd * Dd);
    f2h_k<<<192, 256>>>(sw2, w2h, Dd * Dd);
    f2h_k<<<192, 256>>>(ew1, w3h, Dd * Dd);
    f2h_k<<<192, 256>>>(ew2, w4h, Dd * Dd);
    f2h_k<<<192, 256>>>(W2w, W2h, Cc * 2 * Dd);
    transpose_h<<<dim3(24, 24, Cc), dim3(32, 8)>>>(W1, W1th);

    const dim3 blk(256);
    // MLPs (M=1024, N=768, K=768)
    gemm_h<<<dim3(6, 8, 1), blk, SMEM_BYTES>>>(Xh, 0, Dd, w1h, 0, Dd, Htmph, 0, Dd,
                                               1, sb1, nullptr, nullptr, nullptr, nullptr);
    gemm_h<<<dim3(6, 8, 1), blk, SMEM_BYTES>>>(Htmph, 0, Dd, w2h, 0, Dd, Hsh, 0, Dd,
                                               2, sb2, nullptr, nullptr, nullptr, nullptr);
    gemm_h<<<dim3(6, 8, 1), blk, SMEM_BYTES>>>(Xh, 0, Dd, w3h, 0, Dd, Htmph, 0, Dd,
                                               1, eb1, nullptr, nullptr, nullptr, nullptr);
    gemm_h<<<dim3(6, 8, 1), blk, SMEM_BYTES>>>(Htmph, 0, Dd, w4h, 0, Dd, Heh, 0, Dd,
                                               2, eb2, nullptr, nullptr, nullptr, nullptr);
    // Ls / Le (M=1024, N=256, K=768), float out
    gemm_h<<<dim3(2, 8, 1), blk, SMEM_BYTES>>>(Hsh, 0, Dd, W2h, 0, 2 * Dd, Ls, 0, Cc,
                                               0, nullptr, nullptr, nullptr, nullptr, nullptr);
    gemm_h<<<dim3(2, 8, 1), blk, SMEM_BYTES>>>(Heh, 0, Dd, W2h + Dd, 0, 2 * Dd, Le, 0, Cc,
                                               0, nullptr, nullptr, nullptr, nullptr, nullptr);
    // Phase A: Th[bi, c, e] = sum_d Hsh[bi,d] * W1th[c,e,d]   (z = c), half out
    gemm_h<<<dim3(6, 8, Cc), blk, SMEM_BYTES>>>(Hsh, 0, Dd,
                                                W1th, (long)Dd * Dd, Dd,
                                                Th, (long)Dd, (long)Cc * Dd,
                                                3, nullptr, nullptr, nullptr, nullptr, nullptr);
    // Phase B: out[z, j, c] = sum_e Heh_b[j,e] * Th[z,c,e] + linear   (z = bi)
    gemm_h<<<dim3(2, 4, BLn), blk, SMEM_BYTES>>>(Heh, 0, Dd, Th, 0, Dd, out, 0, Cc,
                                                 4, nullptr, Ls, Le, W2b, bs);
}

// round 8
// speedup vs baseline: 1.8399x; 1.0007x over previous
#include <cuda_runtime.h>
#include <cuda_fp16.h>
#include <cstdint>
#include <cstdio>
#include <cstdlib>
#include <cstring>
#include <dlfcn.h>

#define Dd 768
#define Cc 256
#define BLn 1024

// Scratch (device globals: allocation-free rule)
__device__ __half g_Xh[BLn * Dd];
__device__ __half g_w1h[Dd * Dd];
__device__ __half g_w2h[Dd * Dd];
__device__ __half g_w3h[Dd * Dd];
__device__ __half g_w4h[Dd * Dd];
__device__ __half g_W2h[Cc * 2 * Dd];
__device__ __half g_W1th[(size_t)Cc * Dd * Dd];   // [c][e][d] half
__device__ __half g_Htmph[BLn * Dd];
__device__ __half g_Hsh[BLn * Dd];
__device__ __half g_Heh[BLn * Dd];
__device__ __half g_Th[(size_t)BLn * Cc * Dd];    // T[bi][c][e] half
__device__ float  g_Ls[BLn * Cc];
__device__ float  g_Le[BLn * Cc];
__device__ int    g_bad;

static __device__ __forceinline__ uint32_t smem_u32(const void* p) {
    uint32_t a;
    asm("{ .reg .u64 t; cvta.to.shared.u64 t, %1; cvt.u32.u64 %0, t; }" : "=r"(a) : "l"(p));
    return a;
}
static __device__ __forceinline__ void cp16(uint32_t dst, const void* src) {
    asm volatile("cp.async.cg.shared.global [%0], [%1], 16;" :: "r"(dst), "l"(src) : "memory");
}
static __device__ __forceinline__ void cp_commit() {
    asm volatile("cp.async.commit_group;" ::: "memory");
}
template <int N>
static __device__ __forceinline__ void cp_wait() {
    asm volatile("cp.async.wait_group %0;" :: "n"(N) : "memory");
}
static __device__ __forceinline__ void mma_f16(float& c0, float& c1, float& c2, float& c3,
                                               uint32_t a0, uint32_t a1, uint32_t a2, uint32_t a3,
                                               uint32_t b0, uint32_t b1) {
    asm volatile(
        "mma.sync.aligned.m16n8k16.row.col.f32.f16.f16.f32 "
        "{%0,%1,%2,%3}, {%4,%5,%6,%7}, {%8,%9}, {%0,%1,%2,%3};"
        : "+f"(c0), "+f"(c1), "+f"(c2), "+f"(c3)
        : "r"(a0), "r"(a1), "r"(a2), "r"(a3), "r"(b0), "r"(b1));
}

// ---------------------------------------------------------------------------
// Legacy fp16 mma.sync GEMM (fallback path; proven at 2023us)
// ---------------------------------------------------------------------------
#define ROWH 72
#define ASTG (128 * ROWH)
#define SMEM_BYTES (4 * ASTG * 2 * 2 / 2)  // 73728

__global__ void __launch_bounds__(256, 2)
gemm_h(const __half* A, long saz, int lda,
       const __half* B, long sbz, int ldb,
       void* Cv, long scz, long ldc,
       int mode, const float* __restrict__ b1,
       const float* __restrict__ Lsg, const float* __restrict__ Leg,
       const float* __restrict__ W2bg, const float* __restrict__ biasg)
{
    extern __shared__ __half smh[];
    __half* As = smh;
    __half* Bs = smh + 2 * ASTG;
    const uint32_t sbase = smem_u32(smh);
    const uint32_t bbase = sbase + 2 * ASTG * 2;

    const int tid = threadIdx.x;
    const int z = blockIdx.z;
    float* Cf = (float*)Cv;
    __half* Ch = (__half*)Cv;
    if (mode == 4) {
        A += (long)(z >> 9) * 512 * Dd;
        B += (long)z * Cc * Dd;
        Cf += (long)z * 512 * Cc;
    } else {
        A += z * saz; B += z * sbz;
        Cf += z * scz; Ch += z * scz;
    }
    const int m0 = blockIdx.y * 128, n0 = blockIdx.x * 128;

    const int pr = tid >> 3, pc = tid & 7;
    const __half* pa0 = A + (long)(m0 + pr) * lda + pc * 8;
    const __half* pb0 = B + (long)(n0 + pr) * ldb + pc * 8;
    const uint32_t qoff = (uint32_t)(pr * ROWH * 2 + pc * 16);
    const uint32_t qa0 = sbase + qoff;
    const uint32_t qb0 = bbase + qoff;
    const uint32_t stgb = ASTG * 2;

    float acc[4][4][4];
#pragma unroll
    for (int mi = 0; mi < 4; mi++)
#pragma unroll
        for (int ni = 0; ni < 4; ni++)
#pragma unroll
            for (int r = 0; r < 4; r++) acc[mi][ni][r] = 0.f;

    const int lane = tid & 31, w = tid >> 5;
    const int g = lane >> 2, tig = lane & 3;
    const int wm = w & 1, wn = w >> 1;

#pragma unroll
    for (int i = 0; i < 4; i++) {
        cp16(qa0 + i * (32 * ROWH * 2), pa0 + (long)(32 * i) * lda);
        cp16(qb0 + i * (32 * ROWH * 2), pb0 + (long)(32 * i) * ldb);
    }
    cp_commit();

    for (int k0 = 0; k0 < 12; k0++) {
        cp_wait<0>();
        __syncthreads();
        if (k0 + 1 < 12) {
            const uint32_t so = ((k0 + 1) & 1) * stgb;
            const long go = (long)(k0 + 1) * 64;
#pragma unroll
            for (int i = 0; i < 4; i++) {
                cp16(qa0 + so + i * (32 * ROWH * 2), pa0 + (long)(32 * i) * lda + go);
                cp16(qb0 + so + i * (32 * ROWH * 2), pb0 + (long)(32 * i) * ldb + go);
            }
            cp_commit();
        }

        const __half* aw = As + (k0 & 1) * ASTG + (wm * 64) * ROWH;
        const __half* bw = Bs + (k0 & 1) * ASTG + (wn * 32) * ROWH;

#pragma unroll
        for (int ks = 0; ks < 4; ks++) {
            const int kh = ks * 16 + 2 * tig;
            uint32_t af[4][4], bf[4][2];
#pragma unroll
            for (int mi = 0; mi < 4; mi++) {
                const __half* p = aw + (mi * 16 + g) * ROWH + kh;
                af[mi][0] = *(const uint32_t*)(p);
                af[mi][1] = *(const uint32_t*)(p + 8 * ROWH);
                af[mi][2] = *(const uint32_t*)(p + 8);
                af[mi][3] = *(const uint32_t*)(p + 8 * ROWH + 8);
            }
#pragma unroll
            for (int ni = 0; ni < 4; ni++) {
                const __half* p = bw + (ni * 8 + g) * ROWH + kh;
                bf[ni][0] = *(const uint32_t*)(p);
                bf[ni][1] = *(const uint32_t*)(p + 8);
            }
#pragma unroll
            for (int mi = 0; mi < 4; mi++)
#pragma unroll
                for (int ni = 0; ni < 4; ni++)
                    mma_f16(acc[mi][ni][0], acc[mi][ni][1], acc[mi][ni][2], acc[mi][ni][3],
                            af[mi][0], af[mi][1], af[mi][2], af[mi][3],
                            bf[ni][0], bf[ni][1]);
        }
    }

    const float* lsr = nullptr; const float* leb = nullptr;
    if (mode == 4) {
        lsr = Lsg + (long)z * Cc;
        leb = Leg + (long)(z >> 9) * 512 * Cc;
    }
#pragma unroll
    for (int mi = 0; mi < 4; mi++) {
#pragma unroll
        for (int ni = 0; ni < 4; ni++) {
            const int col = n0 + wn * 32 + ni * 8 + tig * 2;
#pragma unroll
            for (int h = 0; h < 2; h++) {
                const int row = m0 + wm * 64 + mi * 16 + g + h * 8;
                float x0 = acc[mi][ni][h * 2];
                float x1 = acc[mi][ni][h * 2 + 1];
                if (mode == 1) {
                    x0 = fmaxf(x0 + b1[col], 0.f);
                    x1 = fmaxf(x1 + b1[col + 1], 0.f);
                } else if (mode == 2) {
                    x0 += b1[col]; x1 += b1[col + 1];
                } else if (mode == 4) {
                    const float* ler = leb + (long)row * Cc;
                    x0 += lsr[col] + ler[col] + W2bg[col] + biasg[col];
                    x1 += lsr[col + 1] + ler[col + 1] + W2bg[col + 1] + biasg[col + 1];
                }
                if (mode == 0 || mode == 4) {
                    *(float2*)(Cf + (long)row * ldc + col) = make_float2(x0, x1);
                } else {
                    *(__half2*)(Ch + (long)row * ldc + col) = __floats2half2_rn(x0, x1);
                }
            }
        }
    }
}

// W1th[c][e][d] = half(W1[c][d][e])
__global__ void __launch_bounds__(256)
transpose_h(const float* __restrict__ W1, __half* __restrict__ W1t)
{
    __shared__ float ts[32][33];
    const int c = blockIdx.z;
    const float* src = W1 + (size_t)c * Dd * Dd;
    __half* dst = W1t + (size_t)c * Dd * Dd;
    const int d0 = blockIdx.y * 32, e0 = blockIdx.x * 32;
    const int x = threadIdx.x, y = threadIdx.y;
#pragma unroll
    for (int j = 0; j < 32; j += 8)
        ts[y + j][x] = src[(size_t)(d0 + y + j) * Dd + e0 + x];
    __syncthreads();
#pragma unroll
    for (int j = 0; j < 32; j += 8)
        dst[(size_t)(e0 + y + j) * Dd + d0 + x] = __float2half_rn(ts[x][y + j]);
}

__global__ void f2h_k(const float* __restrict__ x, __half* __restrict__ y, int n)
{
    for (int i = blockIdx.x * blockDim.x + threadIdx.x; i < n; i += gridDim.x * blockDim.x)
        y[i] = __float2half_rn(x[i]);
}

__global__ void fillh_k(__half* y, int n, unsigned seed)
{
    for (int i = blockIdx.x * blockDim.x + threadIdx.x; i < n; i += gridDim.x * blockDim.x) {
        unsigned v = (unsigned)i * 2654435761u + seed * 97u;
        y[i] = __float2half_rn((float)((v >> 16) & 1023) / 256.f - 2.f);
    }
}
__global__ void cmp_k(const float* a, const float* b, int n, int* bad)
{
    int i = blockIdx.x * blockDim.x + threadIdx.x;
    if (i < n) {
        float d = fabsf(a[i] - b[i]);
        if (!(d <= 0.1f + 0.004f * fabsf(a[i]))) atomicAdd(bad, 1);
    }
}

// ---------------------------------------------------------------------------
// tcgen05 kernel source, compiled at runtime by NVRTC for sm_103a.
// SS kind::f16: M=128, N=256, K chunk = 64 halves (128B SW128 rows), 12 chunks.
// 288 threads: warps 0-7 producers (cp.async), warp 8 MMA, warps 0-3 epilogue.
// All mbarrier waits are BOUNDED (alive flag) so bugs fail fast, never hang.
// ---------------------------------------------------------------------------
static const char* TC_SRC = R"XX(
typedef unsigned int u32; typedef unsigned long long u64; typedef unsigned short u16;
#define MWAIT(a,p) do{ if(alive){ u32 ok=0; for(int t=0;t<500&&!ok;t++){ \
  asm volatile("{\n\t.reg .pred P;\n\tmbarrier.try_wait.parity.acquire.cta.shared::cta.b64 P, [%1], %2, 0x989680;\n\tselp.b32 %0, 1, 0, P;\n\t}" \
    : "=r"(ok) : "r"(a), "r"(p) : "memory"); } alive = ok; } }while(0)
extern "C" __global__ void __launch_bounds__(288) gtc(
  const u16* A, long long saz, int lda,
  const u16* B, long long sbz, int ldb,
  void* Cv, long long scz, long long ldc,
  int mode, const float* b1, const float* Lsg, const float* Leg,
  const float* W2bg, const float* biasg)
{
  extern __shared__ char smem[];
  u32 raw; asm("{ .reg .u64 t; cvta.to.shared.u64 t, %1; cvt.u32.u64 %0, t; }":"=r"(raw):"l"(smem));
  const u32 data = (raw + 1023) & ~(u32)1023;
  const u32 ctrl = data + 98304;
  const u32 bfl[2] = {ctrl, ctrl + 8};
  const u32 bem[2] = {ctrl + 16, ctrl + 24};
  const u32 bdone = ctrl + 32, btm = ctrl + 40;
  const int tid = threadIdx.x, wid = tid >> 5;
  const int z = blockIdx.z;
  u32 alive = 1;
  const u16* Ap = A; const u16* Bp = B;
  float* Cf = (float*)Cv; u16* Ch = (u16*)Cv;
  if (mode == 4) {
    Ap += (long long)(z >> 9) * (512*768);
    Bp += (long long)z * (256*768);
    Cf += (long long)z * (512*256);
  } else {
    Ap += (long long)z * saz; Bp += (long long)z * sbz;
    Cf += (long long)z * scz; Ch += (long long)z * scz;
  }
  const int m0 = blockIdx.y * 128, n0 = blockIdx.x * 256;
  if (tid == 0) {
    asm volatile("mbarrier.init.shared.b64 [%0], 256;"::"r"(bfl[0]):"memory");
    asm volatile("mbarrier.init.shared.b64 [%0], 256;"::"r"(bfl[1]):"memory");
    asm volatile("mbarrier.init.shared.b64 [%0], 1;"::"r"(bem[0]):"memory");
    asm volatile("mbarrier.init.shared.b64 [%0], 1;"::"r"(bem[1]):"memory");
    asm volatile("mbarrier.init.shared.b64 [%0], 1;"::"r"(bdone):"memory");
  }
  if (wid == 8) {
    asm volatile("tcgen05.alloc.cta_group::1.sync.aligned.shared::cta.b32 [%0], 256;"::"r"(btm):"memory");
    asm volatile("tcgen05.relinquish_alloc_permit.cta_group::1.sync.aligned;");
  }
  __syncthreads();
  u32 tmem; asm volatile("ld.shared.b32 %0, [%1];":"=r"(tmem):"r"(btm));

  if (tid < 256) {
    const u16* pa[4]; u32 qa[2][4];
    #pragma unroll
    for (int i = 0; i < 4; i++) {
      int f = tid + i * 256, r = f >> 3, cu = f & 7;
      pa[i] = Ap + (long long)(m0 + r) * lda + cu * 8;
      u32 off = (u32)(r * 128 + cu * 16); u32 sw = off ^ ((off >> 3) & 0x70);
      qa[0][i] = data + sw; qa[1][i] = data + 16384 + sw;
    }
    const u16* pb[8]; u32 qb[2][8];
    #pragma unroll
    for (int i = 0; i < 8; i++) {
      int f = tid + i * 256, r = f >> 3, cu = f & 7;
      pb[i] = Bp + (long long)(n0 + r) * ldb + cu * 8;
      u32 off = (u32)(r * 128 + cu * 16); u32 sw = off ^ ((off >> 3) & 0x70);
      qb[0][i] = data + 32768 + sw; qb[1][i] = data + 65536 + sw;
    }
    for (int k = 0; k < 12; k++) {
      int s = k & 1;
      if (k >= 2) MWAIT(bem[s], ((k >> 1) - 1) & 1);
      #pragma unroll
      for (int i = 0; i < 4; i++)
        asm volatile("cp.async.cg.shared.global [%0], [%1], 16;"::"r"(qa[s][i]),"l"(pa[i] + k * 64):"memory");
      #pragma unroll
      for (int i = 0; i < 8; i++)
        asm volatile("cp.async.cg.shared.global [%0], [%1], 16;"::"r"(qb[s][i]),"l"(pb[i] + k * 64):"memory");
      asm volatile("cp.async.mbarrier.arrive.shared::cta.b64 [%0];"::"r"(bfl[s]):"memory");
    }
  } else if (wid == 8 && (tid & 31) == 0) {
    const u64 base = (2ULL << 61) | (1ULL << 46) | (64ULL << 32) | (1ULL << 16);
    u64 dA[2] = {base | ((data >> 4) & 0x3FFF), base | (((data + 16384) >> 4) & 0x3FFF)};
    u64 dB[2] = {base | (((data + 32768) >> 4) & 0x3FFF), base | (((data + 65536) >> 4) & 0x3FFF)};
    const u32 idesc = (1u << 4) | (32u << 17) | (8u << 24);
    for (int k = 0; k < 12; k++) {
      int s = k & 1;
      MWAIT(bfl[s], (k >> 1) & 1);
      asm volatile("fence.proxy.async.shared::cta;":::"memory");
      #pragma unroll
      for (int i = 0; i < 4; i++) {
        u32 en = (u32)(k | i);
        asm volatile("{\n\t.reg .pred p;\n\tsetp.ne.u32 p, %4, 0;\n\t"
          "tcgen05.mma.cta_group::1.kind::f16 [%0], %1, %2, %3, {%5,%5,%5,%5}, p;\n\t}"
          ::"r"(tmem),"l"(dA[s] + 2*i),"l"(dB[s] + 2*i),"r"(idesc),"r"(en),"r"(0u):"memory");
      }
      asm volatile("tcgen05.commit.cta_group::1.mbarrier::arrive::one.shared::cluster.b64 [%0];"::"r"(bem[s]):"memory");
    }
    asm volatile("tcgen05.commit.cta_group::1.mbarrier::arrive::one.shared::cluster.b64 [%0];"::"r"(bdone):"memory");
  }

  MWAIT(bdone, 0);
  asm volatile("tcgen05.fence::after_thread_sync;":::"memory");

  if (tid < 128) {
    const long long row = m0 + tid;
    const float* lsr = 0; const float* ler = 0;
    if (mode == 4) {
      lsr = Lsg + (long long)z * 256;
      ler = Leg + ((long long)(z >> 9) * 512 + row) * 256;
    }
    for (int nc = 0; nc < 8; nc++) {
      u32 r[32];
      asm volatile("tcgen05.ld.sync.aligned.32x32b.x32.b32 "
        "{%0,%1,%2,%3,%4,%5,%6,%7,%8,%9,%10,%11,%12,%13,%14,%15,"
        "%16,%17,%18,%19,%20,%21,%22,%23,%24,%25,%26,%27,%28,%29,%30,%31}, [%32];"
        : "=r"(r[0]),"=r"(r[1]),"=r"(r[2]),"=r"(r[3]),"=r"(r[4]),"=r"(r[5]),"=r"(r[6]),"=r"(r[7]),
          "=r"(r[8]),"=r"(r[9]),"=r"(r[10]),"=r"(r[11]),"=r"(r[12]),"=r"(r[13]),"=r"(r[14]),"=r"(r[15]),
          "=r"(r[16]),"=r"(r[17]),"=r"(r[18]),"=r"(r[19]),"=r"(r[20]),"=r"(r[21]),"=r"(r[22]),"=r"(r[23]),
          "=r"(r[24]),"=r"(r[25]),"=r"(r[26]),"=r"(r[27]),"=r"(r[28]),"=r"(r[29]),"=r"(r[30]),"=r"(r[31])
        : "r"(tmem + nc * 32));
      asm volatile("tcgen05.wait::ld.sync.aligned;":::"memory");
      const int nb = n0 + nc * 32;
      float v[32];
      #pragma unroll
      for (int c = 0; c < 32; c++) {
        float x; asm("mov.b32 %0, %1;" : "=f"(x) : "r"(r[c]));
        const int n = nb + c;
        if (mode == 1)      { x = x + b1[n]; x = x > 0.f ? x : 0.f; }
        else if (mode == 2) x = x + b1[n];
        else if (mode == 4) x += lsr[n] + ler[n] + W2bg[n] + biasg[n];
        v[c] = x;
      }
      if (mode == 0 || mode == 4) {
        float* dst = Cf + row * ldc + nb;
        #pragma unroll
        for (int j = 0; j < 8; j++)
          asm volatile("st.global.v4.f32 [%0], {%1,%2,%3,%4};"
            ::"l"(dst + 4*j),"f"(v[4*j]),"f"(v[4*j+1]),"f"(v[4*j+2]),"f"(v[4*j+3]):"memory");
      } else {
        u16* dst = Ch + row * ldc + nb;
        u32 hp[16];
        #pragma unroll
        for (int j = 0; j < 16; j++) {
          asm("{\n\t.reg .b16 lo, hi;\n\tcvt.rn.f16.f32 lo, %1;\n\tcvt.rn.f16.f32 hi, %2;\n\t"
              "mov.b32 %0, {lo, hi};\n\t}" : "=r"(hp[j]) : "f"(v[2*j]), "f"(v[2*j+1]));
        }
        #pragma unroll
        for (int j = 0; j < 4; j++)
          asm volatile("st.global.v4.b32 [%0], {%1,%2,%3,%4};"
            ::"l"(dst + 8*j),"r"(hp[4*j]),"r"(hp[4*j+1]),"r"(hp[4*j+2]),"r"(hp[4*j+3]):"memory");
      }
    }
  }
  __syncthreads();
  if (wid == 8)
    asm volatile("tcgen05.dealloc.cta_group::1.sync.aligned.b32 %0, 256;"::"r"(tmem));
}
)XX";

// ---------------------------------------------------------------------------
// Runtime JIT plumbing (dlopen NVRTC + libcuda; no extra link deps)
// ---------------------------------------------------------------------------
#define TC_SMEM 99392

// CRITICAL: the harness captures the stream that <<<>>> launches use. Since
// legacy-NULL-stream capture is illegal in CUDA, the build must be per-thread
// default stream; driver-API launches must then use CU_STREAM_PER_THREAD (0x2),
// NOT 0 (legacy), or capture breaks (round-7 timeout).
#if defined(CUDA_API_PER_THREAD_DEFAULT_STREAM) || defined(__CUDA_API_PER_THREAD_DEFAULT_STREAM__)
#define HS ((void*)0x2)
#else
#define HS ((void*)0x1)
#endif

typedef int (*nvrtcCreate_t)(void**, const char*, const char*, int, const char* const*, const char* const*);
typedef int (*nvrtcCompile_t)(void*, int, const char* const*);
typedef int (*nvrtcGetSize_t)(void*, size_t*);
typedef int (*nvrtcGetData_t)(void*, char*);
typedef int (*cuModLoad_t)(void**, const void*);
typedef int (*cuModGetFn_t)(void**, void*, const char*);
typedef int (*cuFnSetAttr_t)(void*, int, int);
typedef int (*cuLaunch_t)(void*, unsigned, unsigned, unsigned, unsigned, unsigned, unsigned,
                          unsigned, void*, void**, void**);

static int g_init_done = 0;
static int g_use_tc = 0;
static void* g_fn = nullptr;
static cuLaunch_t p_launch = nullptr;

static int tc_gemm(int gx, int gy, int gz,
                   const void* A, long long saz, int lda,
                   const void* B, long long sbz, int ldb,
                   void* C, long long scz, long long ldc, int mode,
                   const void* b1, const void* Ls, const void* Le,
                   const void* W2b, const void* bias)
{
    void* args[15] = {(void*)&A, (void*)&saz, (void*)&lda, (void*)&B, (void*)&sbz, (void*)&ldb,
                      (void*)&C, (void*)&scz, (void*)&ldc, (void*)&mode, (void*)&b1,
                      (void*)&Ls, (void*)&Le, (void*)&W2b, (void*)&bias};
    return p_launch(g_fn, gx, gy, gz, 288, 1, 1, TC_SMEM, HS, args, 0);
}

static void* try_dlopen(const char* const* names, int n) {
    for (int i = 0; i < n; i++) {
        void* h = dlopen(names[i], RTLD_NOW | RTLD_GLOBAL);
        if (h) return h;
    }
    return nullptr;
}

static void init_tc(__half* Xh, __half* w1h, float* Lsf, float* Lef, int* badp)
{
    const char* nvrtc_names[] = {"libnvrtc.so", "libnvrtc.so.13", "libnvrtc.so.12",
                                 "/usr/local/cuda/lib64/libnvrtc.so"};
    const char* cuda_names[] = {"libcuda.so.1", "libcuda.so"};
    void* hn = try_dlopen(nvrtc_names, 4);
    void* hc = try_dlopen(cuda_names, 2);
    if (!hn || !hc) { fprintf(stderr, "tcjit: dlopen failed nv=%p cu=%p\n", hn, hc); return; }

    auto nCreate = (nvrtcCreate_t)dlsym(hn, "nvrtcCreateProgram");
    auto nCompile = (nvrtcCompile_t)dlsym(hn, "nvrtcCompileProgram");
    auto nCubSz = (nvrtcGetSize_t)dlsym(hn, "nvrtcGetCUBINSize");
    auto nCub = (nvrtcGetData_t)dlsym(hn, "nvrtcGetCUBIN");
    auto nLogSz = (nvrtcGetSize_t)dlsym(hn, "nvrtcGetProgramLogSize");
    auto nLog = (nvrtcGetData_t)dlsym(hn, "nvrtcGetProgramLog");
    auto mLoad = (cuModLoad_t)dlsym(hc, "cuModuleLoadData");
    auto mGetFn = (cuModGetFn_t)dlsym(hc, "cuModuleGetFunction");
    auto fAttr = (cuFnSetAttr_t)dlsym(hc, "cuFuncSetAttribute");
    p_launch = (cuLaunch_t)dlsym(hc, "cuLaunchKernel");
    if (!nCreate || !nCompile || !nCubSz || !nCub || !mLoad || !mGetFn || !fAttr || !p_launch) {
        fprintf(stderr, "tcjit: dlsym failed\n"); return;
    }

    void* prog = nullptr;
    if (nCreate(&prog, TC_SRC, "tc.cu", 0, nullptr, nullptr)) {
        fprintf(stderr, "tcjit: create failed\n"); return;
    }
    const char* opts1[] = {"--gpu-architecture=sm_103a", "--std=c++14"};
    int cres = nCompile(prog, 2, opts1);
    if (cres) {
        if (nLogSz && nLog) {
            size_t ls = 0; nLogSz(prog, &ls);
            if (ls > 1) { char* lg = (char*)malloc(ls + 1); nLog(prog, lg); lg[ls] = 0;
                          fprintf(stderr, "tcjit: compile log:\n%s\n", lg); free(lg); }
        }
        fprintf(stderr, "tcjit: sm_103a compile failed (%d)\n", cres);
        return;
    }
    size_t csz = 0;
    if (nCubSz(prog, &csz) || csz == 0) { fprintf(stderr, "tcjit: cubin size fail\n"); return; }
    char* cub = (char*)malloc(csz);
    nCub(prog, cub);
    void* mod = nullptr;
    int lr = mLoad(&mod, cub);
    free(cub);
    if (lr) { fprintf(stderr, "tcjit: module load failed %d\n", lr); return; }
    if (mGetFn(&g_fn, mod, "gtc")) { fprintf(stderr, "tcjit: getfn failed\n"); return; }
    fAttr(g_fn, 8 /*CU_FUNC_ATTRIBUTE_MAX_DYNAMIC_SHARED_SIZE_BYTES*/, TC_SMEM);

    // ---- validation: legacy vs tcgen05 on synthetic data (hang-proof waits) ----
    fillh_k<<<192, 256>>>(Xh, BLn * Dd, 1u);
    fillh_k<<<192, 256>>>(w1h, Dd * Dd, 7u);
    gemm_h<<<dim3(2, 1, 1), 256, SMEM_BYTES>>>(Xh, 0, Dd, w1h, 0, Dd, (void*)Lsf, 0, Cc,
                                               0, nullptr, nullptr, nullptr, nullptr, nullptr);
    int lres = tc_gemm(1, 1, 1, Xh, 0, Dd, w1h, 0, Dd, Lef, 0, Cc, 0, 0, 0, 0, 0, 0);
    if (lres) { fprintf(stderr, "tcjit: launch failed %d\n", lres); return; }
    cudaMemset(badp, 0, sizeof(int));
    cmp_k<<<128, 256>>>(Lsf, Lef, 128 * Cc, badp);
    cudaError_t serr = cudaDeviceSynchronize();
    if (serr != cudaSuccess) {
        fprintf(stderr, "tcjit: validation sync error: %s\n", cudaGetErrorString(serr));
        return;
    }
    int bad = 1 << 30;
    cudaMemcpy(&bad, badp, sizeof(int), cudaMemcpyDeviceToHost);
    fprintf(stderr, "tcjit: validation mismatches = %d / %d\n", bad, 128 * Cc);
    if (bad == 0) g_use_tc = 1;
}

extern "C" void kernel_launch(void* const* d_in, const int* in_sizes, int n_in,
                              void* d_out, int out_size)
{
    const float* hidden = (const float*)d_in[0];
    const float* sw1 = (const float*)d_in[1];
    const float* sb1 = (const float*)d_in[2];
    const float* sw2 = (const float*)d_in[3];
    const float* sb2 = (const float*)d_in[4];
    const float* ew1 = (const float*)d_in[5];
    const float* eb1 = (const float*)d_in[6];
    const float* ew2 = (const float*)d_in[7];
    const float* eb2 = (const float*)d_in[8];
    const float* W1  = (const float*)d_in[9];
    const float* W2w = (const float*)d_in[10];
    const float* W2b = (const float*)d_in[11];
    const float* bs  = (const float*)d_in[12];
    float* out = (float*)d_out;

    __half *Xh, *w1h, *w2h, *w3h, *w4h, *W2h, *W1th, *Htmph, *Hsh, *Heh, *Th;
    float *Ls, *Le;
    int* badp;
    cudaGetSymbolAddress((void**)&Xh, g_Xh);
    cudaGetSymbolAddress((void**)&w1h, g_w1h);
    cudaGetSymbolAddress((void**)&w2h, g_w2h);
    cudaGetSymbolAddress((void**)&w3h, g_w3h);
    cudaGetSymbolAddress((void**)&w4h, g_w4h);
    cudaGetSymbolAddress((void**)&W2h, g_W2h);
    cudaGetSymbolAddress((void**)&W1th, g_W1th);
    cudaGetSymbolAddress((void**)&Htmph, g_Htmph);
    cudaGetSymbolAddress((void**)&Hsh, g_Hsh);
    cudaGetSymbolAddress((void**)&Heh, g_Heh);
    cudaGetSymbolAddress((void**)&Th, g_Th);
    cudaGetSymbolAddress((void**)&Ls, g_Ls);
    cudaGetSymbolAddress((void**)&Le, g_Le);
    cudaGetSymbolAddress((void**)&badp, g_bad);

    if (!g_init_done) {
        cudaFuncSetAttribute(gemm_h, cudaFuncAttributeMaxDynamicSharedMemorySize, SMEM_BYTES);
        init_tc(Xh, w1h, Ls, Le, badp);
        g_init_done = 1;
    }

    // prep: fp16 conversions + W1 transpose
    f2h_k<<<192, 256>>>(hidden, Xh, BLn * Dd);
    f2h_k<<<192, 256>>>(sw1, w1h, Dd * Dd);
    f2h_k<<<192, 256>>>(sw2, w2h, Dd * Dd);
    f2h_k<<<192, 256>>>(ew1, w3h, Dd * Dd);
    f2h_k<<<192, 256>>>(ew2, w4h, Dd * Dd);
    f2h_k<<<192, 256>>>(W2w, W2h, Cc * 2 * Dd);
    transpose_h<<<dim3(24, 24, Cc), dim3(32, 8)>>>(W1, W1th);

    int tc_ok = 0;
    if (g_use_tc) {
        // first launch doubles as a capture-compat probe
        tc_ok = (tc_gemm(3, 8, 1, Xh, 0, Dd, w1h, 0, Dd, Htmph, 0, Dd, 1, sb1, 0, 0, 0, 0) == 0);
        if (!tc_ok) g_use_tc = 0;
    }
    if (tc_ok) {
        tc_gemm(3, 8, 1, Htmph, 0, Dd, w2h, 0, Dd, Hsh, 0, Dd, 2, sb2, 0, 0, 0, 0);
        tc_gemm(3, 8, 1, Xh, 0, Dd, w3h, 0, Dd, Htmph, 0, Dd, 1, eb1, 0, 0, 0, 0);
        tc_gemm(3, 8, 1, Htmph, 0, Dd, w4h, 0, Dd, Heh, 0, Dd, 2, eb2, 0, 0, 0, 0);
        tc_gemm(1, 8, 1, Hsh, 0, Dd, W2h, 0, 2 * Dd, Ls, 0, Cc, 0, 0, 0, 0, 0, 0);
        tc_gemm(1, 8, 1, Heh, 0, Dd, W2h + Dd, 0, 2 * Dd, Le, 0, Cc, 0, 0, 0, 0, 0, 0);
        tc_gemm(3, 8, Cc, Hsh, 0, Dd, W1th, (long long)Dd * Dd, Dd,
                Th, Dd, (long long)Cc * Dd, 3, 0, 0, 0, 0, 0);
        tc_gemm(1, 4, BLn, Heh, 0, Dd, Th, 0, Dd, out, 0, Cc, 4, 0, Ls, Le, W2b, bs);
    } else {
        const dim3 blk(256);
        gemm_h<<<dim3(6, 8, 1), blk, SMEM_BYTES>>>(Xh, 0, Dd, w1h, 0, Dd, Htmph, 0, Dd,
                                                   1, sb1, nullptr, nullptr, nullptr, nullptr);
        gemm_h<<<dim3(6, 8, 1), blk, SMEM_BYTES>>>(Htmph, 0, Dd, w2h, 0, Dd, Hsh, 0, Dd,
                                                   2, sb2, nullptr, nullptr, nullptr, nullptr);
        gemm_h<<<dim3(6, 8, 1), blk, SMEM_BYTES>>>(Xh, 0, Dd, w3h, 0, Dd, Htmph, 0, Dd,
                                                   1, eb1, nullptr, nullptr, nullptr, nullptr);
        gemm_h<<<dim3(6, 8, 1), blk, SMEM_BYTES>>>(Htmph, 0, Dd, w4h, 0, Dd, Heh, 0, Dd,
                                                   2, eb2, nullptr, nullptr, nullptr, nullptr);
        gemm_h<<<dim3(2, 8, 1), blk, SMEM_BYTES>>>(Hsh, 0, Dd, W2h, 0, 2 * Dd, Ls, 0, Cc,
                                                   0, nullptr, nullptr, nullptr, nullptr, nullptr);
        gemm_h<<<dim3(2, 8, 1), blk, SMEM_BYTES>>>(Heh, 0, Dd, W2h + Dd, 0, 2 * Dd, Le, 0, Cc,
                                                   0, nullptr, nullptr, nullptr, nullptr, nullptr);
        gemm_h<<<dim3(6, 8, Cc), blk, SMEM_BYTES>>>(Hsh, 0, Dd,
                                                    W1th, (long)Dd * Dd, Dd,
                                                    Th, (long)Dd, (long)Cc * Dd,
                                                    3, nullptr, nullptr, nullptr, nullptr, nullptr);
        gemm_h<<<dim3(2, 4, BLn), blk, SMEM_BYTES>>>(Heh, 0, Dd, Th, 0, Dd, out, 0, Cc,
                                                     4, nullptr, Ls, Le, W2b, bs);
    }
}

// round 9
// speedup vs baseline: 2.3863x; 1.2970x over previous
#include <cuda_runtime.h>
#include <cuda_fp16.h>
#include <cstdint>
#include <cstdio>
#include <cstdlib>
#include <cstring>
#include <dlfcn.h>

#define Dd 768
#define Cc 256
#define BLn 1024

// Scratch (device globals: allocation-free rule)
__device__ __half g_Xh[BLn * Dd];
__device__ __half g_w1h[Dd * Dd];
__device__ __half g_w2h[Dd * Dd];
__device__ __half g_w3h[Dd * Dd];
__device__ __half g_w4h[Dd * Dd];
__device__ __half g_W2h[Cc * 2 * Dd];
__device__ __half g_W1th[(size_t)Cc * Dd * Dd];   // [c][e][d] half
__device__ __half g_Htmph[BLn * Dd];
__device__ __half g_Hsh[BLn * Dd];
__device__ __half g_Heh[BLn * Dd];
__device__ __half g_Th[(size_t)BLn * Cc * Dd];    // T[bi][c][e] half
__device__ float  g_Ls[BLn * Cc];
__device__ float  g_Le[BLn * Cc];
__device__ int    g_bad;

static __device__ __forceinline__ uint32_t smem_u32(const void* p) {
    uint32_t a;
    asm("{ .reg .u64 t; cvta.to.shared.u64 t, %1; cvt.u32.u64 %0, t; }" : "=r"(a) : "l"(p));
    return a;
}
static __device__ __forceinline__ void cp16(uint32_t dst, const void* src) {
    asm volatile("cp.async.cg.shared.global [%0], [%1], 16;" :: "r"(dst), "l"(src) : "memory");
}
static __device__ __forceinline__ void cp_commit() {
    asm volatile("cp.async.commit_group;" ::: "memory");
}
template <int N>
static __device__ __forceinline__ void cp_wait() {
    asm volatile("cp.async.wait_group %0;" :: "n"(N) : "memory");
}
static __device__ __forceinline__ void mma_f16(float& c0, float& c1, float& c2, float& c3,
                                               uint32_t a0, uint32_t a1, uint32_t a2, uint32_t a3,
                                               uint32_t b0, uint32_t b1) {
    asm volatile(
        "mma.sync.aligned.m16n8k16.row.col.f32.f16.f16.f32 "
        "{%0,%1,%2,%3}, {%4,%5,%6,%7}, {%8,%9}, {%0,%1,%2,%3};"
        : "+f"(c0), "+f"(c1), "+f"(c2), "+f"(c3)
        : "r"(a0), "r"(a1), "r"(a2), "r"(a3), "r"(b0), "r"(b1));
}

// ---------------------------------------------------------------------------
// Legacy fp16 mma.sync GEMM (fallback path; proven at ~2022us)
// ---------------------------------------------------------------------------
#define ROWH 72
#define ASTG (128 * ROWH)
#define SMEM_BYTES (4 * ASTG * 2 * 2 / 2)  // 73728

__global__ void __launch_bounds__(256, 2)
gemm_h(const __half* A, long saz, int lda,
       const __half* B, long sbz, int ldb,
       void* Cv, long scz, long ldc,
       int mode, const float* __restrict__ b1,
       const float* __restrict__ Lsg, const float* __restrict__ Leg,
       const float* __restrict__ W2bg, const float* __restrict__ biasg)
{
    extern __shared__ __half smh[];
    __half* As = smh;
    __half* Bs = smh + 2 * ASTG;
    const uint32_t sbase = smem_u32(smh);
    const uint32_t bbase = sbase + 2 * ASTG * 2;

    const int tid = threadIdx.x;
    const int z = blockIdx.z;
    float* Cf = (float*)Cv;
    __half* Ch = (__half*)Cv;
    if (mode == 4) {
        A += (long)(z >> 9) * 512 * Dd;
        B += (long)z * Cc * Dd;
        Cf += (long)z * 512 * Cc;
    } else {
        A += z * saz; B += z * sbz;
        Cf += z * scz; Ch += z * scz;
    }
    const int m0 = blockIdx.y * 128, n0 = blockIdx.x * 128;

    const int pr = tid >> 3, pc = tid & 7;
    const __half* pa0 = A + (long)(m0 + pr) * lda + pc * 8;
    const __half* pb0 = B + (long)(n0 + pr) * ldb + pc * 8;
    const uint32_t qoff = (uint32_t)(pr * ROWH * 2 + pc * 16);
    const uint32_t qa0 = sbase + qoff;
    const uint32_t qb0 = bbase + qoff;
    const uint32_t stgb = ASTG * 2;

    float acc[4][4][4];
#pragma unroll
    for (int mi = 0; mi < 4; mi++)
#pragma unroll
        for (int ni = 0; ni < 4; ni++)
#pragma unroll
            for (int r = 0; r < 4; r++) acc[mi][ni][r] = 0.f;

    const int lane = tid & 31, w = tid >> 5;
    const int g = lane >> 2, tig = lane & 3;
    const int wm = w & 1, wn = w >> 1;

#pragma unroll
    for (int i = 0; i < 4; i++) {
        cp16(qa0 + i * (32 * ROWH * 2), pa0 + (long)(32 * i) * lda);
        cp16(qb0 + i * (32 * ROWH * 2), pb0 + (long)(32 * i) * ldb);
    }
    cp_commit();

    for (int k0 = 0; k0 < 12; k0++) {
        cp_wait<0>();
        __syncthreads();
        if (k0 + 1 < 12) {
            const uint32_t so = ((k0 + 1) & 1) * stgb;
            const long go = (long)(k0 + 1) * 64;
#pragma unroll
            for (int i = 0; i < 4; i++) {
                cp16(qa0 + so + i * (32 * ROWH * 2), pa0 + (long)(32 * i) * lda + go);
                cp16(qb0 + so + i * (32 * ROWH * 2), pb0 + (long)(32 * i) * ldb + go);
            }
            cp_commit();
        }

        const __half* aw = As + (k0 & 1) * ASTG + (wm * 64) * ROWH;
        const __half* bw = Bs + (k0 & 1) * ASTG + (wn * 32) * ROWH;

#pragma unroll
        for (int ks = 0; ks < 4; ks++) {
            const int kh = ks * 16 + 2 * tig;
            uint32_t af[4][4], bf[4][2];
#pragma unroll
            for (int mi = 0; mi < 4; mi++) {
                const __half* p = aw + (mi * 16 + g) * ROWH + kh;
                af[mi][0] = *(const uint32_t*)(p);
                af[mi][1] = *(const uint32_t*)(p + 8 * ROWH);
                af[mi][2] = *(const uint32_t*)(p + 8);
                af[mi][3] = *(const uint32_t*)(p + 8 * ROWH + 8);
            }
#pragma unroll
            for (int ni = 0; ni < 4; ni++) {
                const __half* p = bw + (ni * 8 + g) * ROWH + kh;
                bf[ni][0] = *(const uint32_t*)(p);
                bf[ni][1] = *(const uint32_t*)(p + 8);
            }
#pragma unroll
            for (int mi = 0; mi < 4; mi++)
#pragma unroll
                for (int ni = 0; ni < 4; ni++)
                    mma_f16(acc[mi][ni][0], acc[mi][ni][1], acc[mi][ni][2], acc[mi][ni][3],
                            af[mi][0], af[mi][1], af[mi][2], af[mi][3],
                            bf[ni][0], bf[ni][1]);
        }
    }

    const float* lsr = nullptr; const float* leb = nullptr;
    if (mode == 4) {
        lsr = Lsg + (long)z * Cc;
        leb = Leg + (long)(z >> 9) * 512 * Cc;
    }
#pragma unroll
    for (int mi = 0; mi < 4; mi++) {
#pragma unroll
        for (int ni = 0; ni < 4; ni++) {
            const int col = n0 + wn * 32 + ni * 8 + tig * 2;
#pragma unroll
            for (int h = 0; h < 2; h++) {
                const int row = m0 + wm * 64 + mi * 16 + g + h * 8;
                float x0 = acc[mi][ni][h * 2];
                float x1 = acc[mi][ni][h * 2 + 1];
                if (mode == 1) {
                    x0 = fmaxf(x0 + b1[col], 0.f);
                    x1 = fmaxf(x1 + b1[col + 1], 0.f);
                } else if (mode == 2) {
                    x0 += b1[col]; x1 += b1[col + 1];
                } else if (mode == 4) {
                    const float* ler = leb + (long)row * Cc;
                    x0 += lsr[col] + ler[col] + W2bg[col] + biasg[col];
                    x1 += lsr[col + 1] + ler[col + 1] + W2bg[col + 1] + biasg[col + 1];
                }
                if (mode == 0 || mode == 4) {
                    *(float2*)(Cf + (long)row * ldc + col) = make_float2(x0, x1);
                } else {
                    *(__half2*)(Ch + (long)row * ldc + col) = __floats2half2_rn(x0, x1);
                }
            }
        }
    }
}

// W1th[c][e][d] = half(W1[c][d][e])
__global__ void __launch_bounds__(256)
transpose_h(const float* __restrict__ W1, __half* __restrict__ W1t)
{
    __shared__ float ts[32][33];
    const int c = blockIdx.z;
    const float* src = W1 + (size_t)c * Dd * Dd;
    __half* dst = W1t + (size_t)c * Dd * Dd;
    const int d0 = blockIdx.y * 32, e0 = blockIdx.x * 32;
    const int x = threadIdx.x, y = threadIdx.y;
#pragma unroll
    for (int j = 0; j < 32; j += 8)
        ts[y + j][x] = src[(size_t)(d0 + y + j) * Dd + e0 + x];
    __syncthreads();
#pragma unroll
    for (int j = 0; j < 32; j += 8)
        dst[(size_t)(e0 + y + j) * Dd + d0 + x] = __float2half_rn(ts[x][y + j]);
}

__global__ void f2h_k(const float* __restrict__ x, __half* __restrict__ y, int n)
{
    for (int i = blockIdx.x * blockDim.x + threadIdx.x; i < n; i += gridDim.x * blockDim.x)
        y[i] = __float2half_rn(x[i]);
}

__global__ void fillh_k(__half* y, int n, unsigned seed)
{
    for (int i = blockIdx.x * blockDim.x + threadIdx.x; i < n; i += gridDim.x * blockDim.x) {
        unsigned v = (unsigned)i * 2654435761u + seed * 97u;
        y[i] = __float2half_rn((float)((v >> 16) & 1023) / 256.f - 2.f);
    }
}
__global__ void cmp_k(const float* a, const float* b, int n, int* bad)
{
    int i = blockIdx.x * blockDim.x + threadIdx.x;
    if (i < n) {
        float d = fabsf(a[i] - b[i]);
        if (!(d <= 0.25f + 0.01f * fabsf(a[i]))) atomicAdd(bad, 1);
    }
}

// ---------------------------------------------------------------------------
// tcgen05 kernel source, compiled at runtime by NVRTC for sm_103a.
// SS kind::f16: M=128, N=256, K chunk = 64 halves (128B SW128 rows), 12 chunks.
// 288 threads: warps 0-7 producers (cp.async), warp 8 MMA, warps 0-3 epilogue.
// FIX vs round 8: cp.async.mbarrier.arrive.NOINC — the default variant
// increments pending count at issue (net-zero on phase) -> barrier never
// flipped -> 523us wait-timeout seen in ncu. noinc consumes init-count.
// ---------------------------------------------------------------------------
static const char* TC_SRC = R"XX(
typedef unsigned int u32; typedef unsigned long long u64; typedef unsigned short u16;
#define MWAIT(a,p) do{ if(alive){ u32 ok=0; for(int t=0;t<500&&!ok;t++){ \
  asm volatile("{\n\t.reg .pred P;\n\tmbarrier.try_wait.parity.acquire.cta.shared::cta.b64 P, [%1], %2, 0x989680;\n\tselp.b32 %0, 1, 0, P;\n\t}" \
    : "=r"(ok) : "r"(a), "r"(p) : "memory"); } alive = ok; } }while(0)
extern "C" __global__ void __launch_bounds__(288) gtc(
  const u16* A, long long saz, int lda,
  const u16* B, long long sbz, int ldb,
  void* Cv, long long scz, long long ldc,
  int mode, const float* b1, const float* Lsg, const float* Leg,
  const float* W2bg, const float* biasg)
{
  extern __shared__ char smem[];
  u32 raw; asm("{ .reg .u64 t; cvta.to.shared.u64 t, %1; cvt.u32.u64 %0, t; }":"=r"(raw):"l"(smem));
  const u32 data = (raw + 1023) & ~(u32)1023;
  const u32 ctrl = data + 98304;
  const u32 bfl[2] = {ctrl, ctrl + 8};
  const u32 bem[2] = {ctrl + 16, ctrl + 24};
  const u32 bdone = ctrl + 32, btm = ctrl + 40;
  const int tid = threadIdx.x, wid = tid >> 5;
  const int z = blockIdx.z;
  u32 alive = 1;
  const u16* Ap = A; const u16* Bp = B;
  float* Cf = (float*)Cv; u16* Ch = (u16*)Cv;
  if (mode == 4) {
    Ap += (long long)(z >> 9) * (512*768);
    Bp += (long long)z * (256*768);
    Cf += (long long)z * (512*256);
  } else {
    Ap += (long long)z * saz; Bp += (long long)z * sbz;
    Cf += (long long)z * scz; Ch += (long long)z * scz;
  }
  const int m0 = blockIdx.y * 128, n0 = blockIdx.x * 256;
  if (tid == 0) {
    asm volatile("mbarrier.init.shared.b64 [%0], 256;"::"r"(bfl[0]):"memory");
    asm volatile("mbarrier.init.shared.b64 [%0], 256;"::"r"(bfl[1]):"memory");
    asm volatile("mbarrier.init.shared.b64 [%0], 1;"::"r"(bem[0]):"memory");
    asm volatile("mbarrier.init.shared.b64 [%0], 1;"::"r"(bem[1]):"memory");
    asm volatile("mbarrier.init.shared.b64 [%0], 1;"::"r"(bdone):"memory");
  }
  if (wid == 8) {
    asm volatile("tcgen05.alloc.cta_group::1.sync.aligned.shared::cta.b32 [%0], 256;"::"r"(btm):"memory");
    asm volatile("tcgen05.relinquish_alloc_permit.cta_group::1.sync.aligned;");
  }
  __syncthreads();
  u32 tmem; asm volatile("ld.shared.b32 %0, [%1];":"=r"(tmem):"r"(btm));

  if (tid < 256) {
    const u16* pa[4]; u32 qa[2][4];
    #pragma unroll
    for (int i = 0; i < 4; i++) {
      int f = tid + i * 256, r = f >> 3, cu = f & 7;
      pa[i] = Ap + (long long)(m0 + r) * lda + cu * 8;
      u32 off = (u32)(r * 128 + cu * 16); u32 sw = off ^ ((off >> 3) & 0x70);
      qa[0][i] = data + sw; qa[1][i] = data + 16384 + sw;
    }
    const u16* pb[8]; u32 qb[2][8];
    #pragma unroll
    for (int i = 0; i < 8; i++) {
      int f = tid + i * 256, r = f >> 3, cu = f & 7;
      pb[i] = Bp + (long long)(n0 + r) * ldb + cu * 8;
      u32 off = (u32)(r * 128 + cu * 16); u32 sw = off ^ ((off >> 3) & 0x70);
      qb[0][i] = data + 32768 + sw; qb[1][i] = data + 65536 + sw;
    }
    for (int k = 0; k < 12; k++) {
      int s = k & 1;
      if (k >= 2) MWAIT(bem[s], ((k >> 1) - 1) & 1);
      #pragma unroll
      for (int i = 0; i < 4; i++)
        asm volatile("cp.async.cg.shared.global [%0], [%1], 16;"::"r"(qa[s][i]),"l"(pa[i] + k * 64):"memory");
      #pragma unroll
      for (int i = 0; i < 8; i++)
        asm volatile("cp.async.cg.shared.global [%0], [%1], 16;"::"r"(qb[s][i]),"l"(pb[i] + k * 64):"memory");
      asm volatile("cp.async.mbarrier.arrive.noinc.shared::cta.b64 [%0];"::"r"(bfl[s]):"memory");
    }
  } else if (wid == 8 && (tid & 31) == 0) {
    const u64 base = (2ULL << 61) | (1ULL << 46) | (64ULL << 32) | (1ULL << 16);
    u64 dA[2] = {base | ((data >> 4) & 0x3FFF), base | (((data + 16384) >> 4) & 0x3FFF)};
    u64 dB[2] = {base | (((data + 32768) >> 4) & 0x3FFF), base | (((data + 65536) >> 4) & 0x3FFF)};
    const u32 idesc = (1u << 4) | (32u << 17) | (8u << 24);
    for (int k = 0; k < 12; k++) {
      int s = k & 1;
      MWAIT(bfl[s], (k >> 1) & 1);
      asm volatile("fence.proxy.async.shared::cta;":::"memory");
      #pragma unroll
      for (int i = 0; i < 4; i++) {
        u32 en = (u32)(k | i);
        asm volatile("{\n\t.reg .pred p;\n\tsetp.ne.u32 p, %4, 0;\n\t"
          "tcgen05.mma.cta_group::1.kind::f16 [%0], %1, %2, %3, {%5,%5,%5,%5}, p;\n\t}"
          ::"r"(tmem),"l"(dA[s] + 2*i),"l"(dB[s] + 2*i),"r"(idesc),"r"(en),"r"(0u):"memory");
      }
      asm volatile("tcgen05.commit.cta_group::1.mbarrier::arrive::one.shared::cluster.b64 [%0];"::"r"(bem[s]):"memory");
    }
    asm volatile("tcgen05.commit.cta_group::1.mbarrier::arrive::one.shared::cluster.b64 [%0];"::"r"(bdone):"memory");
  }

  MWAIT(bdone, 0);
  asm volatile("tcgen05.fence::after_thread_sync;":::"memory");

  if (tid < 128) {
    const long long row = m0 + tid;
    const float* lsr = 0; const float* ler = 0;
    if (mode == 4) {
      lsr = Lsg + (long long)z * 256;
      ler = Leg + ((long long)(z >> 9) * 512 + row) * 256;
    }
    for (int nc = 0; nc < 8; nc++) {
      u32 r[32];
      asm volatile("tcgen05.ld.sync.aligned.32x32b.x32.b32 "
        "{%0,%1,%2,%3,%4,%5,%6,%7,%8,%9,%10,%11,%12,%13,%14,%15,"
        "%16,%17,%18,%19,%20,%21,%22,%23,%24,%25,%26,%27,%28,%29,%30,%31}, [%32];"
        : "=r"(r[0]),"=r"(r[1]),"=r"(r[2]),"=r"(r[3]),"=r"(r[4]),"=r"(r[5]),"=r"(r[6]),"=r"(r[7]),
          "=r"(r[8]),"=r"(r[9]),"=r"(r[10]),"=r"(r[11]),"=r"(r[12]),"=r"(r[13]),"=r"(r[14]),"=r"(r[15]),
          "=r"(r[16]),"=r"(r[17]),"=r"(r[18]),"=r"(r[19]),"=r"(r[20]),"=r"(r[21]),"=r"(r[22]),"=r"(r[23]),
          "=r"(r[24]),"=r"(r[25]),"=r"(r[26]),"=r"(r[27]),"=r"(r[28]),"=r"(r[29]),"=r"(r[30]),"=r"(r[31])
        : "r"(tmem + nc * 32));
      asm volatile("tcgen05.wait::ld.sync.aligned;":::"memory");
      const int nb = n0 + nc * 32;
      float v[32];
      #pragma unroll
      for (int c = 0; c < 32; c++) {
        float x; asm("mov.b32 %0, %1;" : "=f"(x) : "r"(r[c]));
        const int n = nb + c;
        if (mode == 1)      { x = x + b1[n]; x = x > 0.f ? x : 0.f; }
        else if (mode == 2) x = x + b1[n];
        else if (mode == 4) x += lsr[n] + ler[n] + W2bg[n] + biasg[n];
        v[c] = x;
      }
      if (mode == 0 || mode == 4) {
        float* dst = Cf + row * ldc + nb;
        #pragma unroll
        for (int j = 0; j < 8; j++)
          asm volatile("st.global.v4.f32 [%0], {%1,%2,%3,%4};"
            ::"l"(dst + 4*j),"f"(v[4*j]),"f"(v[4*j+1]),"f"(v[4*j+2]),"f"(v[4*j+3]):"memory");
      } else {
        u16* dst = Ch + row * ldc + nb;
        u32 hp[16];
        #pragma unroll
        for (int j = 0; j < 16; j++) {
          asm("{\n\t.reg .b16 lo, hi;\n\tcvt.rn.f16.f32 lo, %1;\n\tcvt.rn.f16.f32 hi, %2;\n\t"
              "mov.b32 %0, {lo, hi};\n\t}" : "=r"(hp[j]) : "f"(v[2*j]), "f"(v[2*j+1]));
        }
        #pragma unroll
        for (int j = 0; j < 4; j++)
          asm volatile("st.global.v4.b32 [%0], {%1,%2,%3,%4};"
            ::"l"(dst + 8*j),"r"(hp[4*j]),"r"(hp[4*j+1]),"r"(hp[4*j+2]),"r"(hp[4*j+3]):"memory");
      }
    }
  }
  __syncthreads();
  if (wid == 8)
    asm volatile("tcgen05.dealloc.cta_group::1.sync.aligned.b32 %0, 256;"::"r"(tmem));
}
)XX";

// ---------------------------------------------------------------------------
// Runtime JIT plumbing (dlopen NVRTC + libcuda; no extra link deps)
// ---------------------------------------------------------------------------
#define TC_SMEM 99392

// Stream for driver-API launches must match what <<<>>> uses under capture:
// per-thread default stream (CU_STREAM_PER_THREAD = 0x2) when PTDS is on.
#if defined(CUDA_API_PER_THREAD_DEFAULT_STREAM) || defined(__CUDA_API_PER_THREAD_DEFAULT_STREAM__)
#define HS ((void*)0x2)
#else
#define HS ((void*)0x1)
#endif

typedef int (*nvrtcCreate_t)(void**, const char*, const char*, int, const char* const*, const char* const*);
typedef int (*nvrtcCompile_t)(void*, int, const char* const*);
typedef int (*nvrtcGetSize_t)(void*, size_t*);
typedef int (*nvrtcGetData_t)(void*, char*);
typedef int (*cuModLoad_t)(void**, const void*);
typedef int (*cuModGetFn_t)(void**, void*, const char*);
typedef int (*cuFnSetAttr_t)(void*, int, int);
typedef int (*cuLaunch_t)(void*, unsigned, unsigned, unsigned, unsigned, unsigned, unsigned,
                          unsigned, void*, void**, void**);

static int g_init_done = 0;
static int g_use_tc = 0;
static void* g_fn = nullptr;
static cuLaunch_t p_launch = nullptr;

static int tc_gemm(int gx, int gy, int gz,
                   const void* A, long long saz, int lda,
                   const void* B, long long sbz, int ldb,
                   void* C, long long scz, long long ldc, int mode,
                   const void* b1, const void* Ls, const void* Le,
                   const void* W2b, const void* bias)
{
    void* args[15] = {(void*)&A, (void*)&saz, (void*)&lda, (void*)&B, (void*)&sbz, (void*)&ldb,
                      (void*)&C, (void*)&scz, (void*)&ldc, (void*)&mode, (void*)&b1,
                      (void*)&Ls, (void*)&Le, (void*)&W2b, (void*)&bias};
    return p_launch(g_fn, gx, gy, gz, 288, 1, 1, TC_SMEM, HS, args, 0);
}

static void* try_dlopen(const char* const* names, int n) {
    for (int i = 0; i < n; i++) {
        void* h = dlopen(names[i], RTLD_NOW | RTLD_GLOBAL);
        if (h) return h;
    }
    return nullptr;
}

static void init_tc(__half* Xh, __half* w1h, float* Lsf, float* Lef, int* badp)
{
    const char* nvrtc_names[] = {"libnvrtc.so", "libnvrtc.so.13", "libnvrtc.so.12",
                                 "/usr/local/cuda/lib64/libnvrtc.so"};
    const char* cuda_names[] = {"libcuda.so.1", "libcuda.so"};
    void* hn = try_dlopen(nvrtc_names, 4);
    void* hc = try_dlopen(cuda_names, 2);
    if (!hn || !hc) { fprintf(stderr, "tcjit: dlopen failed nv=%p cu=%p\n", hn, hc); return; }

    auto nCreate = (nvrtcCreate_t)dlsym(hn, "nvrtcCreateProgram");
    auto nCompile = (nvrtcCompile_t)dlsym(hn, "nvrtcCompileProgram");
    auto nCubSz = (nvrtcGetSize_t)dlsym(hn, "nvrtcGetCUBINSize");
    auto nCub = (nvrtcGetData_t)dlsym(hn, "nvrtcGetCUBIN");
    auto nLogSz = (nvrtcGetSize_t)dlsym(hn, "nvrtcGetProgramLogSize");
    auto nLog = (nvrtcGetData_t)dlsym(hn, "nvrtcGetProgramLog");
    auto mLoad = (cuModLoad_t)dlsym(hc, "cuModuleLoadData");
    auto mGetFn = (cuModGetFn_t)dlsym(hc, "cuModuleGetFunction");
    auto fAttr = (cuFnSetAttr_t)dlsym(hc, "cuFuncSetAttribute");
    p_launch = (cuLaunch_t)dlsym(hc, "cuLaunchKernel");
    if (!nCreate || !nCompile || !nCubSz || !nCub || !mLoad || !mGetFn || !fAttr || !p_launch) {
        fprintf(stderr, "tcjit: dlsym failed\n"); return;
    }

    void* prog = nullptr;
    if (nCreate(&prog, TC_SRC, "tc.cu", 0, nullptr, nullptr)) {
        fprintf(stderr, "tcjit: create failed\n"); return;
    }
    const char* opts1[] = {"--gpu-architecture=sm_103a", "--std=c++14"};
    int cres = nCompile(prog, 2, opts1);
    if (cres) {
        if (nLogSz && nLog) {
            size_t ls = 0; nLogSz(prog, &ls);
            if (ls > 1) { char* lg = (char*)malloc(ls + 1); nLog(prog, lg); lg[ls] = 0;
                          fprintf(stderr, "tcjit: compile log:\n%s\n", lg); free(lg); }
        }
        fprintf(stderr, "tcjit: sm_103a compile failed (%d)\n", cres);
        return;
    }
    size_t csz = 0;
    if (nCubSz(prog, &csz) || csz == 0) { fprintf(stderr, "tcjit: cubin size fail\n"); return; }
    char* cub = (char*)malloc(csz);
    nCub(prog, cub);
    void* mod = nullptr;
    int lr = mLoad(&mod, cub);
    free(cub);
    if (lr) { fprintf(stderr, "tcjit: module load failed %d\n", lr); return; }
    if (mGetFn(&g_fn, mod, "gtc")) { fprintf(stderr, "tcjit: getfn failed\n"); return; }
    fAttr(g_fn, 8 /*CU_FUNC_ATTRIBUTE_MAX_DYNAMIC_SHARED_SIZE_BYTES*/, TC_SMEM);

    // ---- validation: legacy vs tcgen05 on synthetic data (hang-proof waits) ----
    fillh_k<<<192, 256>>>(Xh, BLn * Dd, 1u);
    fillh_k<<<192, 256>>>(w1h, Dd * Dd, 7u);
    gemm_h<<<dim3(2, 1, 1), 256, SMEM_BYTES>>>(Xh, 0, Dd, w1h, 0, Dd, (void*)Lsf, 0, Cc,
                                               0, nullptr, nullptr, nullptr, nullptr, nullptr);
    int lres = tc_gemm(1, 1, 1, Xh, 0, Dd, w1h, 0, Dd, Lef, 0, Cc, 0, 0, 0, 0, 0, 0);
    if (lres) { fprintf(stderr, "tcjit: launch failed %d\n", lres); return; }
    cudaMemset(badp, 0, sizeof(int));
    cmp_k<<<128, 256>>>(Lsf, Lef, 128 * Cc, badp);
    cudaError_t serr = cudaDeviceSynchronize();
    if (serr != cudaSuccess) {
        fprintf(stderr, "tcjit: validation sync error: %s\n", cudaGetErrorString(serr));
        return;
    }
    int bad = 1 << 30;
    cudaMemcpy(&bad, badp, sizeof(int), cudaMemcpyDeviceToHost);
    fprintf(stderr, "tcjit: validation mismatches = %d / %d\n", bad, 128 * Cc);
    if (bad == 0) g_use_tc = 1;
}

extern "C" void kernel_launch(void* const* d_in, const int* in_sizes, int n_in,
                              void* d_out, int out_size)
{
    const float* hidden = (const float*)d_in[0];
    const float* sw1 = (const float*)d_in[1];
    const float* sb1 = (const float*)d_in[2];
    const float* sw2 = (const float*)d_in[3];
    const float* sb2 = (const float*)d_in[4];
    const float* ew1 = (const float*)d_in[5];
    const float* eb1 = (const float*)d_in[6];
    const float* ew2 = (const float*)d_in[7];
    const float* eb2 = (const float*)d_in[8];
    const float* W1  = (const float*)d_in[9];
    const float* W2w = (const float*)d_in[10];
    const float* W2b = (const float*)d_in[11];
    const float* bs  = (const float*)d_in[12];
    float* out = (float*)d_out;

    __half *Xh, *w1h, *w2h, *w3h, *w4h, *W2h, *W1th, *Htmph, *Hsh, *Heh, *Th;
    float *Ls, *Le;
    int* badp;
    cudaGetSymbolAddress((void**)&Xh, g_Xh);
    cudaGetSymbolAddress((void**)&w1h, g_w1h);
    cudaGetSymbolAddress((void**)&w2h, g_w2h);
    cudaGetSymbolAddress((void**)&w3h, g_w3h);
    cudaGetSymbolAddress((void**)&w4h, g_w4h);
    cudaGetSymbolAddress((void**)&W2h, g_W2h);
    cudaGetSymbolAddress((void**)&W1th, g_W1th);
    cudaGetSymbolAddress((void**)&Htmph, g_Htmph);
    cudaGetSymbolAddress((void**)&Hsh, g_Hsh);
    cudaGetSymbolAddress((void**)&Heh, g_Heh);
    cudaGetSymbolAddress((void**)&Th, g_Th);
    cudaGetSymbolAddress((void**)&Ls, g_Ls);
    cudaGetSymbolAddress((void**)&Le, g_Le);
    cudaGetSymbolAddress((void**)&badp, g_bad);

    if (!g_init_done) {
        cudaFuncSetAttribute(gemm_h, cudaFuncAttributeMaxDynamicSharedMemorySize, SMEM_BYTES);
        init_tc(Xh, w1h, Ls, Le, badp);
        g_init_done = 1;
    }

    // prep: fp16 conversions + W1 transpose
    f2h_k<<<192, 256>>>(hidden, Xh, BLn * Dd);
    f2h_k<<<192, 256>>>(sw1, w1h, Dd * Dd);
    f2h_k<<<192, 256>>>(sw2, w2h, Dd * Dd);
    f2h_k<<<192, 256>>>(ew1, w3h, Dd * Dd);
    f2h_k<<<192, 256>>>(ew2, w4h, Dd * Dd);
    f2h_k<<<192, 256>>>(W2w, W2h, Cc * 2 * Dd);
    transpose_h<<<dim3(24, 24, Cc), dim3(32, 8)>>>(W1, W1th);

    int tc_ok = 0;
    if (g_use_tc) {
        tc_ok = (tc_gemm(3, 8, 1, Xh, 0, Dd, w1h, 0, Dd, Htmph, 0, Dd, 1, sb1, 0, 0, 0, 0) == 0);
        if (!tc_ok) g_use_tc = 0;
    }
    if (tc_ok) {
        tc_gemm(3, 8, 1, Htmph, 0, Dd, w2h, 0, Dd, Hsh, 0, Dd, 2, sb2, 0, 0, 0, 0);
        tc_gemm(3, 8, 1, Xh, 0, Dd, w3h, 0, Dd, Htmph, 0, Dd, 1, eb1, 0, 0, 0, 0);
        tc_gemm(3, 8, 1, Htmph, 0, Dd, w4h, 0, Dd, Heh, 0, Dd, 2, eb2, 0, 0, 0, 0);
        tc_gemm(1, 8, 1, Hsh, 0, Dd, W2h, 0, 2 * Dd, Ls, 0, Cc, 0, 0, 0, 0, 0, 0);
        tc_gemm(1, 8, 1, Heh, 0, Dd, W2h + Dd, 0, 2 * Dd, Le, 0, Cc, 0, 0, 0, 0, 0, 0);
        tc_gemm(3, 8, Cc, Hsh, 0, Dd, W1th, (long long)Dd * Dd, Dd,
                Th, Dd, (long long)Cc * Dd, 3, 0, 0, 0, 0, 0);
        tc_gemm(1, 4, BLn, Heh, 0, Dd, Th, 0, Dd, out, 0, Cc, 4, 0, Ls, Le, W2b, bs);
    } else {
        const dim3 blk(256);
        gemm_h<<<dim3(6, 8, 1), blk, SMEM_BYTES>>>(Xh, 0, Dd, w1h, 0, Dd, Htmph, 0, Dd,
                                                   1, sb1, nullptr, nullptr, nullptr, nullptr);
        gemm_h<<<dim3(6, 8, 1), blk, SMEM_BYTES>>>(Htmph, 0, Dd, w2h, 0, Dd, Hsh, 0, Dd,
                                                   2, sb2, nullptr, nullptr, nullptr, nullptr);
        gemm_h<<<dim3(6, 8, 1), blk, SMEM_BYTES>>>(Xh, 0, Dd, w3h, 0, Dd, Htmph, 0, Dd,
                                                   1, eb1, nullptr, nullptr, nullptr, nullptr);
        gemm_h<<<dim3(6, 8, 1), blk, SMEM_BYTES>>>(Htmph, 0, Dd, w4h, 0, Dd, Heh, 0, Dd,
                                                   2, eb2, nullptr, nullptr, nullptr, nullptr);
        gemm_h<<<dim3(2, 8, 1), blk, SMEM_BYTES>>>(Hsh, 0, Dd, W2h, 0, 2 * Dd, Ls, 0, Cc,
                                                   0, nullptr, nullptr, nullptr, nullptr, nullptr);
        gemm_h<<<dim3(2, 8, 1), blk, SMEM_BYTES>>>(Heh, 0, Dd, W2h + Dd, 0, 2 * Dd, Le, 0, Cc,
                                                   0, nullptr, nullptr, nullptr, nullptr, nullptr);
        gemm_h<<<dim3(6, 8, Cc), blk, SMEM_BYTES>>>(Hsh, 0, Dd,
                                                    W1th, (long)Dd * Dd, Dd,
                                                    Th, (long)Dd, (long)Cc * Dd,
                                                    3, nullptr, nullptr, nullptr, nullptr, nullptr);
        gemm_h<<<dim3(2, 4, BLn), blk, SMEM_BYTES>>>(Heh, 0, Dd, Th, 0, Dd, out, 0, Cc,
                                                     4, nullptr, Ls, Le, W2b, bs);
    }
}

// round 10
// speedup vs baseline: 2.4279x; 1.0174x over previous
#include <cuda_runtime.h>
#include <cuda_fp16.h>
#include <cstdint>
#include <cstdio>
#include <cstdlib>
#include <cstring>
#include <dlfcn.h>

#define Dd 768
#define Cc 256
#define BLn 1024

// Scratch (device globals: allocation-free rule)
__device__ __half g_Xh[BLn * Dd];
__device__ __half g_w1h[Dd * Dd];
__device__ __half g_w2h[Dd * Dd];
__device__ __half g_w3h[Dd * Dd];
__device__ __half g_w4h[Dd * Dd];
__device__ __half g_W2h[Cc * 2 * Dd];
__device__ __half g_W1th[(size_t)Cc * Dd * Dd];   // [c][e][d] half
__device__ __half g_Htmph[BLn * Dd];
__device__ __half g_Hsh[BLn * Dd];
__device__ __half g_Heh[BLn * Dd];
__device__ __half g_Th[(size_t)BLn * Cc * Dd];    // T[bi][c][e] half
__device__ float  g_Ls[BLn * Cc];
__device__ float  g_Le[BLn * Cc];
__device__ int    g_bad;

static __device__ __forceinline__ uint32_t smem_u32(const void* p) {
    uint32_t a;
    asm("{ .reg .u64 t; cvta.to.shared.u64 t, %1; cvt.u32.u64 %0, t; }" : "=r"(a) : "l"(p));
    return a;
}
static __device__ __forceinline__ void cp16(uint32_t dst, const void* src) {
    asm volatile("cp.async.cg.shared.global [%0], [%1], 16;" :: "r"(dst), "l"(src) : "memory");
}
static __device__ __forceinline__ void cp_commit() {
    asm volatile("cp.async.commit_group;" ::: "memory");
}
template <int N>
static __device__ __forceinline__ void cp_wait() {
    asm volatile("cp.async.wait_group %0;" :: "n"(N) : "memory");
}
static __device__ __forceinline__ void mma_f16(float& c0, float& c1, float& c2, float& c3,
                                               uint32_t a0, uint32_t a1, uint32_t a2, uint32_t a3,
                                               uint32_t b0, uint32_t b1) {
    asm volatile(
        "mma.sync.aligned.m16n8k16.row.col.f32.f16.f16.f32 "
        "{%0,%1,%2,%3}, {%4,%5,%6,%7}, {%8,%9}, {%0,%1,%2,%3};"
        : "+f"(c0), "+f"(c1), "+f"(c2), "+f"(c3)
        : "r"(a0), "r"(a1), "r"(a2), "r"(a3), "r"(b0), "r"(b1));
}

// ---------------------------------------------------------------------------
// Legacy fp16 mma.sync GEMM (fallback + validation reference; ~2022us path)
// ---------------------------------------------------------------------------
#define ROWH 72
#define ASTG (128 * ROWH)
#define SMEM_BYTES (4 * ASTG * 2 * 2 / 2)  // 73728

__global__ void __launch_bounds__(256, 2)
gemm_h(const __half* A, long saz, int lda,
       const __half* B, long sbz, int ldb,
       void* Cv, long scz, long ldc,
       int mode, const float* __restrict__ b1,
       const float* __restrict__ Lsg, const float* __restrict__ Leg,
       const float* __restrict__ W2bg, const float* __restrict__ biasg)
{
    extern __shared__ __half smh[];
    __half* As = smh;
    __half* Bs = smh + 2 * ASTG;
    const uint32_t sbase = smem_u32(smh);
    const uint32_t bbase = sbase + 2 * ASTG * 2;

    const int tid = threadIdx.x;
    const int z = blockIdx.z;
    float* Cf = (float*)Cv;
    __half* Ch = (__half*)Cv;
    if (mode == 4) {
        A += (long)(z >> 9) * 512 * Dd;
        B += (long)z * Cc * Dd;
        Cf += (long)z * 512 * Cc;
    } else {
        A += z * saz; B += z * sbz;
        Cf += z * scz; Ch += z * scz;
    }
    const int m0 = blockIdx.y * 128, n0 = blockIdx.x * 128;

    const int pr = tid >> 3, pc = tid & 7;
    const __half* pa0 = A + (long)(m0 + pr) * lda + pc * 8;
    const __half* pb0 = B + (long)(n0 + pr) * ldb + pc * 8;
    const uint32_t qoff = (uint32_t)(pr * ROWH * 2 + pc * 16);
    const uint32_t qa0 = sbase + qoff;
    const uint32_t qb0 = bbase + qoff;
    const uint32_t stgb = ASTG * 2;

    float acc[4][4][4];
#pragma unroll
    for (int mi = 0; mi < 4; mi++)
#pragma unroll
        for (int ni = 0; ni < 4; ni++)
#pragma unroll
            for (int r = 0; r < 4; r++) acc[mi][ni][r] = 0.f;

    const int lane = tid & 31, w = tid >> 5;
    const int g = lane >> 2, tig = lane & 3;
    const int wm = w & 1, wn = w >> 1;

#pragma unroll
    for (int i = 0; i < 4; i++) {
        cp16(qa0 + i * (32 * ROWH * 2), pa0 + (long)(32 * i) * lda);
        cp16(qb0 + i * (32 * ROWH * 2), pb0 + (long)(32 * i) * ldb);
    }
    cp_commit();

    for (int k0 = 0; k0 < 12; k0++) {
        cp_wait<0>();
        __syncthreads();
        if (k0 + 1 < 12) {
            const uint32_t so = ((k0 + 1) & 1) * stgb;
            const long go = (long)(k0 + 1) * 64;
#pragma unroll
            for (int i = 0; i < 4; i++) {
                cp16(qa0 + so + i * (32 * ROWH * 2), pa0 + (long)(32 * i) * lda + go);
                cp16(qb0 + so + i * (32 * ROWH * 2), pb0 + (long)(32 * i) * ldb + go);
            }
            cp_commit();
        }

        const __half* aw = As + (k0 & 1) * ASTG + (wm * 64) * ROWH;
        const __half* bw = Bs + (k0 & 1) * ASTG + (wn * 32) * ROWH;

#pragma unroll
        for (int ks = 0; ks < 4; ks++) {
            const int kh = ks * 16 + 2 * tig;
            uint32_t af[4][4], bf[4][2];
#pragma unroll
            for (int mi = 0; mi < 4; mi++) {
                const __half* p = aw + (mi * 16 + g) * ROWH + kh;
                af[mi][0] = *(const uint32_t*)(p);
                af[mi][1] = *(const uint32_t*)(p + 8 * ROWH);
                af[mi][2] = *(const uint32_t*)(p + 8);
                af[mi][3] = *(const uint32_t*)(p + 8 * ROWH + 8);
            }
#pragma unroll
            for (int ni = 0; ni < 4; ni++) {
                const __half* p = bw + (ni * 8 + g) * ROWH + kh;
                bf[ni][0] = *(const uint32_t*)(p);
                bf[ni][1] = *(const uint32_t*)(p + 8);
            }
#pragma unroll
            for (int mi = 0; mi < 4; mi++)
#pragma unroll
                for (int ni = 0; ni < 4; ni++)
                    mma_f16(acc[mi][ni][0], acc[mi][ni][1], acc[mi][ni][2], acc[mi][ni][3],
                            af[mi][0], af[mi][1], af[mi][2], af[mi][3],
                            bf[ni][0], bf[ni][1]);
        }
    }

    const float* lsr = nullptr; const float* leb = nullptr;
    if (mode == 4) {
        lsr = Lsg + (long)z * Cc;
        leb = Leg + (long)(z >> 9) * 512 * Cc;
    }
#pragma unroll
    for (int mi = 0; mi < 4; mi++) {
#pragma unroll
        for (int ni = 0; ni < 4; ni++) {
            const int col = n0 + wn * 32 + ni * 8 + tig * 2;
#pragma unroll
            for (int h = 0; h < 2; h++) {
                const int row = m0 + wm * 64 + mi * 16 + g + h * 8;
                float x0 = acc[mi][ni][h * 2];
                float x1 = acc[mi][ni][h * 2 + 1];
                if (mode == 1) {
                    x0 = fmaxf(x0 + b1[col], 0.f);
                    x1 = fmaxf(x1 + b1[col + 1], 0.f);
                } else if (mode == 2) {
                    x0 += b1[col]; x1 += b1[col + 1];
                } else if (mode == 4) {
                    const float* ler = leb + (long)row * Cc;
                    x0 += lsr[col] + ler[col] + W2bg[col] + biasg[col];
                    x1 += lsr[col + 1] + ler[col + 1] + W2bg[col + 1] + biasg[col + 1];
                }
                if (mode == 0 || mode == 4) {
                    *(float2*)(Cf + (long)row * ldc + col) = make_float2(x0, x1);
                } else {
                    *(__half2*)(Ch + (long)row * ldc + col) = __floats2half2_rn(x0, x1);
                }
            }
        }
    }
}

// W1th[c][e][d] = half(W1[c][d][e])
__global__ void __launch_bounds__(256)
transpose_h(const float* __restrict__ W1, __half* __restrict__ W1t)
{
    __shared__ float ts[32][33];
    const int c = blockIdx.z;
    const float* src = W1 + (size_t)c * Dd * Dd;
    __half* dst = W1t + (size_t)c * Dd * Dd;
    const int d0 = blockIdx.y * 32, e0 = blockIdx.x * 32;
    const int x = threadIdx.x, y = threadIdx.y;
#pragma unroll
    for (int j = 0; j < 32; j += 8)
        ts[y + j][x] = src[(size_t)(d0 + y + j) * Dd + e0 + x];
    __syncthreads();
#pragma unroll
    for (int j = 0; j < 32; j += 8)
        dst[(size_t)(e0 + y + j) * Dd + d0 + x] = __float2half_rn(ts[x][y + j]);
}

__global__ void f2h_k(const float* __restrict__ x, __half* __restrict__ y, int n)
{
    for (int i = blockIdx.x * blockDim.x + threadIdx.x; i < n; i += gridDim.x * blockDim.x)
        y[i] = __float2half_rn(x[i]);
}

__global__ void fillh_k(__half* y, int n, unsigned seed)
{
    for (int i = blockIdx.x * blockDim.x + threadIdx.x; i < n; i += gridDim.x * blockDim.x) {
        unsigned v = (unsigned)i * 2654435761u + seed * 97u;
        y[i] = __float2half_rn((float)((v >> 16) & 1023) / 256.f - 2.f);
    }
}
__global__ void cmp_k(const float* a, const float* b, int n, int* bad)
{
    int i = blockIdx.x * blockDim.x + threadIdx.x;
    if (i < n) {
        float d = fabsf(a[i] - b[i]);
        if (!(d <= 0.25f + 0.01f * fabsf(a[i]))) atomicAdd(bad, 1);
    }
}

// ---------------------------------------------------------------------------
// tcgen05 kernel (NVRTC, sm_103a). Round-10 upgrade vs round 9:
//  * M=256 per CTA: TWO TMEM accumulators (D0 cols 0-255, D1 cols 256-511),
//    B tile loaded ONCE per chunk for both -> halves L2 B-traffic.
//  * 3-stage cp.async ring (3 x 64KB) for deeper load/MMA overlap.
//  * epilogue: warps 0-3 drain D0, warps 4-7 drain D1 in parallel.
// 288 threads: 0-255 producers+epilogue, warp 8 MMA issue.
// ---------------------------------------------------------------------------
static const char* TC_SRC = R"XX(
typedef unsigned int u32; typedef unsigned long long u64; typedef unsigned short u16;
#define MWAIT(a,p) do{ if(alive){ u32 ok=0; for(int t=0;t<2000&&!ok;t++){ \
  asm volatile("{\n\t.reg .pred P;\n\tmbarrier.try_wait.parity.acquire.cta.shared::cta.b64 P, [%1], %2, 0x989680;\n\tselp.b32 %0, 1, 0, P;\n\t}" \
    : "=r"(ok) : "r"(a), "r"(p) : "memory"); } alive = ok; } }while(0)
extern "C" __global__ void __launch_bounds__(288) gtc(
  const u16* A, long long saz, int lda,
  const u16* B, long long sbz, int ldb,
  void* Cv, long long scz, long long ldc,
  int mode, const float* b1, const float* Lsg, const float* Leg,
  const float* W2bg, const float* biasg)
{
  extern __shared__ char smem[];
  u32 raw; asm("{ .reg .u64 t; cvta.to.shared.u64 t, %1; cvt.u32.u64 %0, t; }":"=r"(raw):"l"(smem));
  const u32 data = (raw + 1023) & ~(u32)1023;
  const u32 ctrl = data + 196608;
  const u32 bfl[3] = {ctrl, ctrl + 8, ctrl + 16};
  const u32 bem[3] = {ctrl + 24, ctrl + 32, ctrl + 40};
  const u32 bdone = ctrl + 48, btm = ctrl + 56;
  const int tid = threadIdx.x, wid = tid >> 5;
  const int z = blockIdx.z;
  u32 alive = 1;
  const u16* Ap = A; const u16* Bp = B;
  float* Cf = (float*)Cv; u16* Ch = (u16*)Cv;
  if (mode == 4) {
    Ap += (long long)(z >> 9) * (512*768);
    Bp += (long long)z * (256*768);
    Cf += (long long)z * (512*256);
  } else {
    Ap += (long long)z * saz; Bp += (long long)z * sbz;
    Cf += (long long)z * scz; Ch += (long long)z * scz;
  }
  const int m0 = blockIdx.y * 256, n0 = blockIdx.x * 256;
  if (tid == 0) {
    asm volatile("mbarrier.init.shared.b64 [%0], 256;"::"r"(bfl[0]):"memory");
    asm volatile("mbarrier.init.shared.b64 [%0], 256;"::"r"(bfl[1]):"memory");
    asm volatile("mbarrier.init.shared.b64 [%0], 256;"::"r"(bfl[2]):"memory");
    asm volatile("mbarrier.init.shared.b64 [%0], 1;"::"r"(bem[0]):"memory");
    asm volatile("mbarrier.init.shared.b64 [%0], 1;"::"r"(bem[1]):"memory");
    asm volatile("mbarrier.init.shared.b64 [%0], 1;"::"r"(bem[2]):"memory");
    asm volatile("mbarrier.init.shared.b64 [%0], 1;"::"r"(bdone):"memory");
  }
  if (wid == 8) {
    asm volatile("tcgen05.alloc.cta_group::1.sync.aligned.shared::cta.b32 [%0], 512;"::"r"(btm):"memory");
    asm volatile("tcgen05.relinquish_alloc_permit.cta_group::1.sync.aligned;");
  }
  __syncthreads();
  u32 tmem; asm volatile("ld.shared.b32 %0, [%1];":"=r"(tmem):"r"(btm));

  // stage layout: stage s at data + s*65536: A (256 rows x 128B = 32KB) then B (32KB)
  if (tid < 256) {
    const u16* pa[8]; const u16* pb[8]; u32 qa0[8], qb0[8];
    #pragma unroll
    for (int i = 0; i < 8; i++) {
      int f = tid + i * 256, r = f >> 3, cu = f & 7;
      pa[i] = Ap + (long long)(m0 + r) * lda + cu * 8;
      pb[i] = Bp + (long long)(n0 + r) * ldb + cu * 8;
      u32 off = (u32)(r * 128 + cu * 16); u32 sw = off ^ ((off >> 3) & 0x70);
      qa0[i] = data + sw; qb0[i] = data + 32768 + sw;
    }
    int s = 0, ph = 0;
    for (int k = 0; k < 12; k++) {
      if (k >= 3) MWAIT(bem[s], ph ^ 1);
      const u32 so = (u32)s * 65536;
      #pragma unroll
      for (int i = 0; i < 8; i++)
        asm volatile("cp.async.cg.shared.global [%0], [%1], 16;"::"r"(qa0[i] + so),"l"(pa[i] + k * 64):"memory");
      #pragma unroll
      for (int i = 0; i < 8; i++)
        asm volatile("cp.async.cg.shared.global [%0], [%1], 16;"::"r"(qb0[i] + so),"l"(pb[i] + k * 64):"memory");
      asm volatile("cp.async.mbarrier.arrive.noinc.shared::cta.b64 [%0];"::"r"(bfl[s]):"memory");
      if (++s == 3) { s = 0; ph ^= 1; }
    }
  } else if (wid == 8 && (tid & 31) == 0) {
    const u64 base = (2ULL << 61) | (1ULL << 46) | (64ULL << 32) | (1ULL << 16);
    const u64 d0 = base | ((data >> 4) & 0x3FFF);
    const u32 idesc = (1u << 4) | (32u << 17) | (8u << 24);
    int s = 0, ph = 0;
    for (int k = 0; k < 12; k++) {
      MWAIT(bfl[s], ph);
      asm volatile("fence.proxy.async.shared::cta;":::"memory");
      u64 dstage = d0 + (u64)s * 4096;   // 65536B / 16
      u64 dA0 = dstage, dA1 = dstage + 1024, dB = dstage + 2048;
      #pragma unroll
      for (int i = 0; i < 4; i++) {
        u32 en = (u32)(k | i);
        asm volatile("{\n\t.reg .pred p;\n\tsetp.ne.u32 p, %4, 0;\n\t"
          "tcgen05.mma.cta_group::1.kind::f16 [%0], %1, %2, %3, {%5,%5,%5,%5}, p;\n\t}"
          ::"r"(tmem),"l"(dA0 + 2*i),"l"(dB + 2*i),"r"(idesc),"r"(en),"r"(0u):"memory");
      }
      #pragma unroll
      for (int i = 0; i < 4; i++) {
        u32 en = (u32)(k | i);
        asm volatile("{\n\t.reg .pred p;\n\tsetp.ne.u32 p, %4, 0;\n\t"
          "tcgen05.mma.cta_group::1.kind::f16 [%0], %1, %2, %3, {%5,%5,%5,%5}, p;\n\t}"
          ::"r"(tmem + 256),"l"(dA1 + 2*i),"l"(dB + 2*i),"r"(idesc),"r"(en),"r"(0u):"memory");
      }
      asm volatile("tcgen05.commit.cta_group::1.mbarrier::arrive::one.shared::cluster.b64 [%0];"::"r"(bem[s]):"memory");
      if (++s == 3) { s = 0; ph ^= 1; }
    }
    asm volatile("tcgen05.commit.cta_group::1.mbarrier::arrive::one.shared::cluster.b64 [%0];"::"r"(bdone):"memory");
  }

  MWAIT(bdone, 0);
  asm volatile("tcgen05.fence::after_thread_sync;":::"memory");

  if (tid < 256) {
    const int grp = tid >> 7;           // 0 -> D0 rows m0..m0+127, 1 -> D1 rows m0+128..
    const int lt = tid & 127;
    const long long row = m0 + grp * 128 + lt;
    const u32 tbase = tmem + (u32)grp * 256;
    const float* lsr = 0; const float* ler = 0;
    if (mode == 4) {
      lsr = Lsg + (long long)z * 256;
      ler = Leg + ((long long)(z >> 9) * 512 + row) * 256;
    }
    for (int nc = 0; nc < 8; nc++) {
      u32 r[32];
      asm volatile("tcgen05.ld.sync.aligned.32x32b.x32.b32 "
        "{%0,%1,%2,%3,%4,%5,%6,%7,%8,%9,%10,%11,%12,%13,%14,%15,"
        "%16,%17,%18,%19,%20,%21,%22,%23,%24,%25,%26,%27,%28,%29,%30,%31}, [%32];"
        : "=r"(r[0]),"=r"(r[1]),"=r"(r[2]),"=r"(r[3]),"=r"(r[4]),"=r"(r[5]),"=r"(r[6]),"=r"(r[7]),
          "=r"(r[8]),"=r"(r[9]),"=r"(r[10]),"=r"(r[11]),"=r"(r[12]),"=r"(r[13]),"=r"(r[14]),"=r"(r[15]),
          "=r"(r[16]),"=r"(r[17]),"=r"(r[18]),"=r"(r[19]),"=r"(r[20]),"=r"(r[21]),"=r"(r[22]),"=r"(r[23]),
          "=r"(r[24]),"=r"(r[25]),"=r"(r[26]),"=r"(r[27]),"=r"(r[28]),"=r"(r[29]),"=r"(r[30]),"=r"(r[31])
        : "r"(tbase + nc * 32));
      asm volatile("tcgen05.wait::ld.sync.aligned;":::"memory");
      const int nb = n0 + nc * 32;
      float v[32];
      #pragma unroll
      for (int c = 0; c < 32; c++) {
        float x; asm("mov.b32 %0, %1;" : "=f"(x) : "r"(r[c]));
        const int n = nb + c;
        if (mode == 1)      { x = x + b1[n]; x = x > 0.f ? x : 0.f; }
        else if (mode == 2) x = x + b1[n];
        else if (mode == 4) x += lsr[n] + ler[n] + W2bg[n] + biasg[n];
        v[c] = x;
      }
      if (mode == 0 || mode == 4) {
        float* dst = Cf + row * ldc + nb;
        #pragma unroll
        for (int j = 0; j < 8; j++)
          asm volatile("st.global.v4.f32 [%0], {%1,%2,%3,%4};"
            ::"l"(dst + 4*j),"f"(v[4*j]),"f"(v[4*j+1]),"f"(v[4*j+2]),"f"(v[4*j+3]):"memory");
      } else {
        u16* dst = Ch + row * ldc + nb;
        u32 hp[16];
        #pragma unroll
        for (int j = 0; j < 16; j++) {
          asm("{\n\t.reg .b16 lo, hi;\n\tcvt.rn.f16.f32 lo, %1;\n\tcvt.rn.f16.f32 hi, %2;\n\t"
              "mov.b32 %0, {lo, hi};\n\t}" : "=r"(hp[j]) : "f"(v[2*j]), "f"(v[2*j+1]));
        }
        #pragma unroll
        for (int j = 0; j < 4; j++)
          asm volatile("st.global.v4.b32 [%0], {%1,%2,%3,%4};"
            ::"l"(dst + 8*j),"r"(hp[4*j]),"r"(hp[4*j+1]),"r"(hp[4*j+2]),"r"(hp[4*j+3]):"memory");
      }
    }
  }
  __syncthreads();
  if (wid == 8)
    asm volatile("tcgen05.dealloc.cta_group::1.sync.aligned.b32 %0, 512;"::"r"(tmem));
}
)XX";

// ---------------------------------------------------------------------------
// Runtime JIT plumbing (dlopen NVRTC + libcuda; no extra link deps)
// ---------------------------------------------------------------------------
#define TC_SMEM 197760   // 3 stages * 64KB + ctrl + 1KB align slack (< 227KB cap)

// Stream for driver-API launches must match what <<<>>> uses under capture:
// per-thread default stream (CU_STREAM_PER_THREAD = 0x2) when PTDS is on.
#if defined(CUDA_API_PER_THREAD_DEFAULT_STREAM) || defined(__CUDA_API_PER_THREAD_DEFAULT_STREAM__)
#define HS ((void*)0x2)
#else
#define HS ((void*)0x1)
#endif

typedef int (*nvrtcCreate_t)(void**, const char*, const char*, int, const char* const*, const char* const*);
typedef int (*nvrtcCompile_t)(void*, int, const char* const*);
typedef int (*nvrtcGetSize_t)(void*, size_t*);
typedef int (*nvrtcGetData_t)(void*, char*);
typedef int (*cuModLoad_t)(void**, const void*);
typedef int (*cuModGetFn_t)(void**, void*, const char*);
typedef int (*cuFnSetAttr_t)(void*, int, int);
typedef int (*cuLaunch_t)(void*, unsigned, unsigned, unsigned, unsigned, unsigned, unsigned,
                          unsigned, void*, void**, void**);

static int g_init_done = 0;
static int g_use_tc = 0;
static void* g_fn = nullptr;
static cuLaunch_t p_launch = nullptr;

static int tc_gemm(int gx, int gy, int gz,
                   const void* A, long long saz, int lda,
                   const void* B, long long sbz, int ldb,
                   void* C, long long scz, long long ldc, int mode,
                   const void* b1, const void* Ls, const void* Le,
                   const void* W2b, const void* bias)
{
    void* args[15] = {(void*)&A, (void*)&saz, (void*)&lda, (void*)&B, (void*)&sbz, (void*)&ldb,
                      (void*)&C, (void*)&scz, (void*)&ldc, (void*)&mode, (void*)&b1,
                      (void*)&Ls, (void*)&Le, (void*)&W2b, (void*)&bias};
    return p_launch(g_fn, gx, gy, gz, 288, 1, 1, TC_SMEM, HS, args, 0);
}

static void* try_dlopen(const char* const* names, int n) {
    for (int i = 0; i < n; i++) {
        void* h = dlopen(names[i], RTLD_NOW | RTLD_GLOBAL);
        if (h) return h;
    }
    return nullptr;
}

static void init_tc(__half* Xh, __half* w1h, float* Lsf, float* Lef, int* badp)
{
    const char* nvrtc_names[] = {"libnvrtc.so", "libnvrtc.so.13", "libnvrtc.so.12",
                                 "/usr/local/cuda/lib64/libnvrtc.so"};
    const char* cuda_names[] = {"libcuda.so.1", "libcuda.so"};
    void* hn = try_dlopen(nvrtc_names, 4);
    void* hc = try_dlopen(cuda_names, 2);
    if (!hn || !hc) { fprintf(stderr, "tcjit: dlopen failed nv=%p cu=%p\n", hn, hc); return; }

    auto nCreate = (nvrtcCreate_t)dlsym(hn, "nvrtcCreateProgram");
    auto nCompile = (nvrtcCompile_t)dlsym(hn, "nvrtcCompileProgram");
    auto nCubSz = (nvrtcGetSize_t)dlsym(hn, "nvrtcGetCUBINSize");
    auto nCub = (nvrtcGetData_t)dlsym(hn, "nvrtcGetCUBIN");
    auto nLogSz = (nvrtcGetSize_t)dlsym(hn, "nvrtcGetProgramLogSize");
    auto nLog = (nvrtcGetData_t)dlsym(hn, "nvrtcGetProgramLog");
    auto mLoad = (cuModLoad_t)dlsym(hc, "cuModuleLoadData");
    auto mGetFn = (cuModGetFn_t)dlsym(hc, "cuModuleGetFunction");
    auto fAttr = (cuFnSetAttr_t)dlsym(hc, "cuFuncSetAttribute");
    p_launch = (cuLaunch_t)dlsym(hc, "cuLaunchKernel");
    if (!nCreate || !nCompile || !nCubSz || !nCub || !mLoad || !mGetFn || !fAttr || !p_launch) {
        fprintf(stderr, "tcjit: dlsym failed\n"); return;
    }

    void* prog = nullptr;
    if (nCreate(&prog, TC_SRC, "tc.cu", 0, nullptr, nullptr)) {
        fprintf(stderr, "tcjit: create failed\n"); return;
    }
    const char* opts1[] = {"--gpu-architecture=sm_103a", "--std=c++14"};
    int cres = nCompile(prog, 2, opts1);
    if (cres) {
        if (nLogSz && nLog) {
            size_t ls = 0; nLogSz(prog, &ls);
            if (ls > 1) { char* lg = (char*)malloc(ls + 1); nLog(prog, lg); lg[ls] = 0;
                          fprintf(stderr, "tcjit: compile log:\n%s\n", lg); free(lg); }
        }
        fprintf(stderr, "tcjit: sm_103a compile failed (%d)\n", cres);
        return;
    }
    size_t csz = 0;
    if (nCubSz(prog, &csz) || csz == 0) { fprintf(stderr, "tcjit: cubin size fail\n"); return; }
    char* cub = (char*)malloc(csz);
    nCub(prog, cub);
    void* mod = nullptr;
    int lr = mLoad(&mod, cub);
    free(cub);
    if (lr) { fprintf(stderr, "tcjit: module load failed %d\n", lr); return; }
    if (mGetFn(&g_fn, mod, "gtc")) { fprintf(stderr, "tcjit: getfn failed\n"); return; }
    fAttr(g_fn, 8 /*CU_FUNC_ATTRIBUTE_MAX_DYNAMIC_SHARED_SIZE_BYTES*/, TC_SMEM);

    // ---- validation: legacy (256x256) vs tcgen05 M=256 tile (hang-proof) ----
    fillh_k<<<192, 256>>>(Xh, BLn * Dd, 1u);
    fillh_k<<<192, 256>>>(w1h, Dd * Dd, 7u);
    gemm_h<<<dim3(2, 2, 1), 256, SMEM_BYTES>>>(Xh, 0, Dd, w1h, 0, Dd, (void*)Lsf, 0, Cc,
                                               0, nullptr, nullptr, nullptr, nullptr, nullptr);
    int lres = tc_gemm(1, 1, 1, Xh, 0, Dd, w1h, 0, Dd, Lef, 0, Cc, 0, 0, 0, 0, 0, 0);
    if (lres) { fprintf(stderr, "tcjit: launch failed %d\n", lres); return; }
    cudaMemset(badp, 0, sizeof(int));
    cmp_k<<<256, 256>>>(Lsf, Lef, 256 * Cc, badp);
    cudaError_t serr = cudaDeviceSynchronize();
    if (serr != cudaSuccess) {
        fprintf(stderr, "tcjit: validation sync error: %s\n", cudaGetErrorString(serr));
        return;
    }
    int bad = 1 << 30;
    cudaMemcpy(&bad, badp, sizeof(int), cudaMemcpyDeviceToHost);
    fprintf(stderr, "tcjit: validation mismatches = %d / %d\n", bad, 256 * Cc);
    if (bad == 0) g_use_tc = 1;
}

extern "C" void kernel_launch(void* const* d_in, const int* in_sizes, int n_in,
                              void* d_out, int out_size)
{
    const float* hidden = (const float*)d_in[0];
    const float* sw1 = (const float*)d_in[1];
    const float* sb1 = (const float*)d_in[2];
    const float* sw2 = (const float*)d_in[3];
    const float* sb2 = (const float*)d_in[4];
    const float* ew1 = (const float*)d_in[5];
    const float* eb1 = (const float*)d_in[6];
    const float* ew2 = (const float*)d_in[7];
    const float* eb2 = (const float*)d_in[8];
    const float* W1  = (const float*)d_in[9];
    const float* W2w = (const float*)d_in[10];
    const float* W2b = (const float*)d_in[11];
    const float* bs  = (const float*)d_in[12];
    float* out = (float*)d_out;

    __half *Xh, *w1h, *w2h, *w3h, *w4h, *W2h, *W1th, *Htmph, *Hsh, *Heh, *Th;
    float *Ls, *Le;
    int* badp;
    cudaGetSymbolAddress((void**)&Xh, g_Xh);
    cudaGetSymbolAddress((void**)&w1h, g_w1h);
    cudaGetSymbolAddress((void**)&w2h, g_w2h);
    cudaGetSymbolAddress((void**)&w3h, g_w3h);
    cudaGetSymbolAddress((void**)&w4h, g_w4h);
    cudaGetSymbolAddress((void**)&W2h, g_W2h);
    cudaGetSymbolAddress((void**)&W1th, g_W1th);
    cudaGetSymbolAddress((void**)&Htmph, g_Htmph);
    cudaGetSymbolAddress((void**)&Hsh, g_Hsh);
    cudaGetSymbolAddress((void**)&Heh, g_Heh);
    cudaGetSymbolAddress((void**)&Th, g_Th);
    cudaGetSymbolAddress((void**)&Ls, g_Ls);
    cudaGetSymbolAddress((void**)&Le, g_Le);
    cudaGetSymbolAddress((void**)&badp, g_bad);

    if (!g_init_done) {
        cudaFuncSetAttribute(gemm_h, cudaFuncAttributeMaxDynamicSharedMemorySize, SMEM_BYTES);
        init_tc(Xh, w1h, Ls, Le, badp);
        g_init_done = 1;
    }

    // prep: fp16 conversions + W1 transpose
    f2h_k<<<192, 256>>>(hidden, Xh, BLn * Dd);
    f2h_k<<<192, 256>>>(sw1, w1h, Dd * Dd);
    f2h_k<<<192, 256>>>(sw2, w2h, Dd * Dd);
    f2h_k<<<192, 256>>>(ew1, w3h, Dd * Dd);
    f2h_k<<<192, 256>>>(ew2, w4h, Dd * Dd);
    f2h_k<<<192, 256>>>(W2w, W2h, Cc * 2 * Dd);
    transpose_h<<<dim3(24, 24, Cc), dim3(32, 8)>>>(W1, W1th);

    int tc_ok = 0;
    if (g_use_tc) {
        // MLPs: M=1024 (4 m-pairs), N=768 (3 n-tiles), K=768
        tc_ok = (tc_gemm(3, 4, 1, Xh, 0, Dd, w1h, 0, Dd, Htmph, 0, Dd, 1, sb1, 0, 0, 0, 0) == 0);
        if (!tc_ok) g_use_tc = 0;
    }
    if (tc_ok) {
        tc_gemm(3, 4, 1, Htmph, 0, Dd, w2h, 0, Dd, Hsh, 0, Dd, 2, sb2, 0, 0, 0, 0);
        tc_gemm(3, 4, 1, Xh, 0, Dd, w3h, 0, Dd, Htmph, 0, Dd, 1, eb1, 0, 0, 0, 0);
        tc_gemm(3, 4, 1, Htmph, 0, Dd, w4h, 0, Dd, Heh, 0, Dd, 2, eb2, 0, 0, 0, 0);
        // Ls / Le: M=1024, N=256
        tc_gemm(1, 4, 1, Hsh, 0, Dd, W2h, 0, 2 * Dd, Ls, 0, Cc, 0, 0, 0, 0, 0, 0);
        tc_gemm(1, 4, 1, Heh, 0, Dd, W2h + Dd, 0, 2 * Dd, Le, 0, Cc, 0, 0, 0, 0, 0, 0);
        // Phase A: z = c, M=1024 (4 m-pairs), N=768 (3 e-tiles)
        tc_gemm(3, 4, Cc, Hsh, 0, Dd, W1th, (long long)Dd * Dd, Dd,
                Th, Dd, (long long)Cc * Dd, 3, 0, 0, 0, 0, 0);
        // Phase B: z = bi, M=512 (2 m-pairs), N=256
        tc_gemm(1, 2, BLn, Heh, 0, Dd, Th, 0, Dd, out, 0, Cc, 4, 0, Ls, Le, W2b, bs);
    } else {
        const dim3 blk(256);
        gemm_h<<<dim3(6, 8, 1), blk, SMEM_BYTES>>>(Xh, 0, Dd, w1h, 0, Dd, Htmph, 0, Dd,
                                                   1, sb1, nullptr, nullptr, nullptr, nullptr);
        gemm_h<<<dim3(6, 8, 1), blk, SMEM_BYTES>>>(Htmph, 0, Dd, w2h, 0, Dd, Hsh, 0, Dd,
                                                   2, sb2, nullptr, nullptr, nullptr, nullptr);
        gemm_h<<<dim3(6, 8, 1), blk, SMEM_BYTES>>>(Xh, 0, Dd, w3h, 0, Dd, Htmph, 0, Dd,
                                                   1, eb1, nullptr, nullptr, nullptr, nullptr);
        gemm_h<<<dim3(6, 8, 1), blk, SMEM_BYTES>>>(Htmph, 0, Dd, w4h, 0, Dd, Heh, 0, Dd,
                                                   2, eb2, nullptr, nullptr, nullptr, nullptr);
        gemm_h<<<dim3(2, 8, 1), blk, SMEM_BYTES>>>(Hsh, 0, Dd, W2h, 0, 2 * Dd, Ls, 0, Cc,
                                                   0, nullptr, nullptr, nullptr, nullptr, nullptr);
        gemm_h<<<dim3(2, 8, 1), blk, SMEM_BYTES>>>(Heh, 0, Dd, W2h + Dd, 0, 2 * Dd, Le, 0, Cc,
                                                   0, nullptr, nullptr, nullptr, nullptr, nullptr);
        gemm_h<<<dim3(6, 8, Cc), blk, SMEM_BYTES>>>(Hsh, 0, Dd,
                                                    W1th, (long)Dd * Dd, Dd,
                                                    Th, (long)Dd, (long)Cc * Dd,
                                                    3, nullptr, nullptr, nullptr, nullptr, nullptr);
        gemm_h<<<dim3(2, 4, BLn), blk, SMEM_BYTES>>>(Heh, 0, Dd, Th, 0, Dd, out, 0, Cc,
                                                     4, nullptr, Ls, Le, W2b, bs);
    }
}

// round 11
// speedup vs baseline: 2.5761x; 1.0611x over previous
#include <cuda_runtime.h>
#include <cuda_fp16.h>
#include <cstdint>
#include <cstdio>
#include <cstdlib>
#include <cstring>
#include <dlfcn.h>

#define Dd 768
#define Cc 256
#define BLn 1024
#define HD (Dd * Dd)          // 589824
#define BLD (BLn * Dd)        // 786432
#define BLC (BLn * Cc)        // 262144

// Scratch (device globals: allocation-free rule; zero-initialized)
__device__ __half g_Xh[BLD];
__device__ __half g_w13h[2 * HD];                 // sw1 || ew1
__device__ __half g_w24h[2 * HD];                 // sw2 || ew2
__device__ __half g_W2h[Cc * 2 * Dd];
__device__ __half g_W1th[(size_t)Cc * Dd * Dd];   // [c][e][d] half
__device__ __half g_Htmp2[2 * BLD];               // s-hidden || e-hidden
__device__ __half g_HsHe[2 * BLD];                // Hs || He
__device__ __half g_Th[(size_t)BLn * Cc * Dd];    // T[bi][c][e] half
__device__ float  g_LsLe[2 * BLC];                // Ls || Le
__device__ float  g_b1x[2 * Dd];                  // sb1 || eb1
__device__ float  g_b2x[2 * Dd];                  // sb2 || eb2
__device__ int    g_bad;

static __device__ __forceinline__ uint32_t smem_u32(const void* p) {
    uint32_t a;
    asm("{ .reg .u64 t; cvta.to.shared.u64 t, %1; cvt.u32.u64 %0, t; }" : "=r"(a) : "l"(p));
    return a;
}
static __device__ __forceinline__ void cp16(uint32_t dst, const void* src) {
    asm volatile("cp.async.cg.shared.global [%0], [%1], 16;" :: "r"(dst), "l"(src) : "memory");
}
static __device__ __forceinline__ void cp_commit() {
    asm volatile("cp.async.commit_group;" ::: "memory");
}
template <int N>
static __device__ __forceinline__ void cp_wait() {
    asm volatile("cp.async.wait_group %0;" :: "n"(N) : "memory");
}
static __device__ __forceinline__ void mma_f16(float& c0, float& c1, float& c2, float& c3,
                                               uint32_t a0, uint32_t a1, uint32_t a2, uint32_t a3,
                                               uint32_t b0, uint32_t b1) {
    asm volatile(
        "mma.sync.aligned.m16n8k16.row.col.f32.f16.f16.f32 "
        "{%0,%1,%2,%3}, {%4,%5,%6,%7}, {%8,%9}, {%0,%1,%2,%3};"
        : "+f"(c0), "+f"(c1), "+f"(c2), "+f"(c3)
        : "r"(a0), "r"(a1), "r"(a2), "r"(a3), "r"(b0), "r"(b1));
}

// ---------------------------------------------------------------------------
// Legacy fp16 mma.sync GEMM (fallback + validation reference; ~2022us path)
// ---------------------------------------------------------------------------
#define ROWH 72
#define ASTG (128 * ROWH)
#define SMEM_BYTES (4 * ASTG * 2 * 2 / 2)  // 73728

__global__ void __launch_bounds__(256, 2)
gemm_h(const __half* A, long saz, int lda,
       const __half* B, long sbz, int ldb,
       void* Cv, long scz, long ldc,
       int mode, const float* __restrict__ b1,
       const float* __restrict__ Lsg, const float* __restrict__ Leg,
       const float* __restrict__ W2bg, const float* __restrict__ biasg)
{
    extern __shared__ __half smh[];
    __half* As = smh;
    __half* Bs = smh + 2 * ASTG;
    const uint32_t sbase = smem_u32(smh);
    const uint32_t bbase = sbase + 2 * ASTG * 2;

    const int tid = threadIdx.x;
    const int z = blockIdx.z;
    float* Cf = (float*)Cv;
    __half* Ch = (__half*)Cv;
    if (mode == 4) {
        A += (long)(z >> 9) * 512 * Dd;
        B += (long)z * Cc * Dd;
        Cf += (long)z * 512 * Cc;
    } else {
        A += z * saz; B += z * sbz;
        Cf += z * scz; Ch += z * scz;
    }
    const int m0 = blockIdx.y * 128, n0 = blockIdx.x * 128;

    const int pr = tid >> 3, pc = tid & 7;
    const __half* pa0 = A + (long)(m0 + pr) * lda + pc * 8;
    const __half* pb0 = B + (long)(n0 + pr) * ldb + pc * 8;
    const uint32_t qoff = (uint32_t)(pr * ROWH * 2 + pc * 16);
    const uint32_t qa0 = sbase + qoff;
    const uint32_t qb0 = bbase + qoff;
    const uint32_t stgb = ASTG * 2;

    float acc[4][4][4];
#pragma unroll
    for (int mi = 0; mi < 4; mi++)
#pragma unroll
        for (int ni = 0; ni < 4; ni++)
#pragma unroll
            for (int r = 0; r < 4; r++) acc[mi][ni][r] = 0.f;

    const int lane = tid & 31, w = tid >> 5;
    const int g = lane >> 2, tig = lane & 3;
    const int wm = w & 1, wn = w >> 1;

#pragma unroll
    for (int i = 0; i < 4; i++) {
        cp16(qa0 + i * (32 * ROWH * 2), pa0 + (long)(32 * i) * lda);
        cp16(qb0 + i * (32 * ROWH * 2), pb0 + (long)(32 * i) * ldb);
    }
    cp_commit();

    for (int k0 = 0; k0 < 12; k0++) {
        cp_wait<0>();
        __syncthreads();
        if (k0 + 1 < 12) {
            const uint32_t so = ((k0 + 1) & 1) * stgb;
            const long go = (long)(k0 + 1) * 64;
#pragma unroll
            for (int i = 0; i < 4; i++) {
                cp16(qa0 + so + i * (32 * ROWH * 2), pa0 + (long)(32 * i) * lda + go);
                cp16(qb0 + so + i * (32 * ROWH * 2), pb0 + (long)(32 * i) * ldb + go);
            }
            cp_commit();
        }

        const __half* aw = As + (k0 & 1) * ASTG + (wm * 64) * ROWH;
        const __half* bw = Bs + (k0 & 1) * ASTG + (wn * 32) * ROWH;

#pragma unroll
        for (int ks = 0; ks < 4; ks++) {
            const int kh = ks * 16 + 2 * tig;
            uint32_t af[4][4], bf[4][2];
#pragma unroll
            for (int mi = 0; mi < 4; mi++) {
                const __half* p = aw + (mi * 16 + g) * ROWH + kh;
                af[mi][0] = *(const uint32_t*)(p);
                af[mi][1] = *(const uint32_t*)(p + 8 * ROWH);
                af[mi][2] = *(const uint32_t*)(p + 8);
                af[mi][3] = *(const uint32_t*)(p + 8 * ROWH + 8);
            }
#pragma unroll
            for (int ni = 0; ni < 4; ni++) {
                const __half* p = bw + (ni * 8 + g) * ROWH + kh;
                bf[ni][0] = *(const uint32_t*)(p);
                bf[ni][1] = *(const uint32_t*)(p + 8);
            }
#pragma unroll
            for (int mi = 0; mi < 4; mi++)
#pragma unroll
                for (int ni = 0; ni < 4; ni++)
                    mma_f16(acc[mi][ni][0], acc[mi][ni][1], acc[mi][ni][2], acc[mi][ni][3],
                            af[mi][0], af[mi][1], af[mi][2], af[mi][3],
                            bf[ni][0], bf[ni][1]);
        }
    }

    const float* lsr = nullptr; const float* leb = nullptr;
    if (mode == 4) {
        lsr = Lsg + (long)z * Cc;
        leb = Leg + (long)(z >> 9) * 512 * Cc;
    }
#pragma unroll
    for (int mi = 0; mi < 4; mi++) {
#pragma unroll
        for (int ni = 0; ni < 4; ni++) {
            const int col = n0 + wn * 32 + ni * 8 + tig * 2;
#pragma unroll
            for (int h = 0; h < 2; h++) {
                const int row = m0 + wm * 64 + mi * 16 + g + h * 8;
                float x0 = acc[mi][ni][h * 2];
                float x1 = acc[mi][ni][h * 2 + 1];
                if (mode == 1) {
                    x0 = fmaxf(x0 + b1[col], 0.f);
                    x1 = fmaxf(x1 + b1[col + 1], 0.f);
                } else if (mode == 2) {
                    x0 += b1[col]; x1 += b1[col + 1];
                } else if (mode == 4) {
                    const float* ler = leb + (long)row * Cc;
                    x0 += lsr[col] + ler[col] + W2bg[col] + biasg[col];
                    x1 += lsr[col + 1] + ler[col + 1] + W2bg[col + 1] + biasg[col + 1];
                }
                if (mode == 0 || mode == 4) {
                    *(float2*)(Cf + (long)row * ldc + col) = make_float2(x0, x1);
                } else {
                    *(__half2*)(Ch + (long)row * ldc + col) = __floats2half2_rn(x0, x1);
                }
            }
        }
    }
}

// W1th[c][e][d] = half(W1[c][d][e])
__global__ void __launch_bounds__(256)
transpose_h(const float* __restrict__ W1, __half* __restrict__ W1t)
{
    __shared__ float ts[32][33];
    const int c = blockIdx.z;
    const float* src = W1 + (size_t)c * Dd * Dd;
    __half* dst = W1t + (size_t)c * Dd * Dd;
    const int d0 = blockIdx.y * 32, e0 = blockIdx.x * 32;
    const int x = threadIdx.x, y = threadIdx.y;
#pragma unroll
    for (int j = 0; j < 32; j += 8)
        ts[y + j][x] = src[(size_t)(d0 + y + j) * Dd + e0 + x];
    __syncthreads();
#pragma unroll
    for (int j = 0; j < 32; j += 8)
        dst[(size_t)(e0 + y + j) * Dd + d0 + x] = __float2half_rn(ts[x][y + j]);
}

// Fused f32->f16 conversion for all six tensors in ONE launch
__global__ void f2h_multi(const float* __restrict__ hidden,
                          const float* __restrict__ sw1, const float* __restrict__ ew1,
                          const float* __restrict__ sw2, const float* __restrict__ ew2,
                          const float* __restrict__ W2w,
                          __half* Xh, __half* w13, __half* w24, __half* W2h)
{
    const int total = BLD + 4 * HD + Cc * 2 * Dd;   // 3538944
    for (int i = blockIdx.x * blockDim.x + threadIdx.x; i < total;
         i += gridDim.x * blockDim.x) {
        int j = i;
        if (j < BLD) { Xh[j] = __float2half_rn(hidden[j]); continue; }
        j -= BLD;
        if (j < HD) { w13[j] = __float2half_rn(sw1[j]); continue; }
        j -= HD;
        if (j < HD) { w13[HD + j] = __float2half_rn(ew1[j]); continue; }
        j -= HD;
        if (j < HD) { w24[j] = __float2half_rn(sw2[j]); continue; }
        j -= HD;
        if (j < HD) { w24[HD + j] = __float2half_rn(ew2[j]); continue; }
        j -= HD;
        W2h[j] = __float2half_rn(W2w[j]);
    }
}

__global__ void biascpy(const float* a, const float* b, const float* c, const float* d,
                        float* b1x, float* b2x)
{
    int i = blockIdx.x * blockDim.x + threadIdx.x;
    if (i < Dd) {
        b1x[i] = a[i]; b1x[Dd + i] = b[i];
        b2x[i] = c[i]; b2x[Dd + i] = d[i];
    }
}

__global__ void fillh_k(__half* y, int n, unsigned seed)
{
    for (int i = blockIdx.x * blockDim.x + threadIdx.x; i < n; i += gridDim.x * blockDim.x) {
        unsigned v = (unsigned)i * 2654435761u + seed * 97u;
        y[i] = __float2half_rn((float)((v >> 16) & 1023) / 256.f - 2.f);
    }
}
__global__ void cmp_k(const float* a, const float* b, int n, int* bad)
{
    int i = blockIdx.x * blockDim.x + threadIdx.x;
    if (i < n) {
        float d = fabsf(a[i] - b[i]);
        if (!(d <= 0.25f + 0.01f * fabsf(a[i]))) atomicAdd(bad, 1);
    }
}

// ---------------------------------------------------------------------------
// tcgen05 kernel (NVRTC, sm_103a). Same proven mainloop as round 10
// (M=256 dual-TMEM, 3-stage cp.async ring); adds bstr (per-z bias stride)
// so the s- and e-MLPs batch into single launches.
// ---------------------------------------------------------------------------
static const char* TC_SRC = R"XX(
typedef unsigned int u32; typedef unsigned long long u64; typedef unsigned short u16;
#define MWAIT(a,p) do{ if(alive){ u32 ok=0; for(int t=0;t<2000&&!ok;t++){ \
  asm volatile("{\n\t.reg .pred P;\n\tmbarrier.try_wait.parity.acquire.cta.shared::cta.b64 P, [%1], %2, 0x989680;\n\tselp.b32 %0, 1, 0, P;\n\t}" \
    : "=r"(ok) : "r"(a), "r"(p) : "memory"); } alive = ok; } }while(0)
extern "C" __global__ void __launch_bounds__(288) gtc(
  const u16* A, long long saz, int lda,
  const u16* B, long long sbz, int ldb,
  void* Cv, long long scz, long long ldc,
  int mode, const float* b1, long long bstr,
  const float* Lsg, const float* Leg, const float* W2bg, const float* biasg)
{
  extern __shared__ char smem[];
  u32 raw; asm("{ .reg .u64 t; cvta.to.shared.u64 t, %1; cvt.u32.u64 %0, t; }":"=r"(raw):"l"(smem));
  const u32 data = (raw + 1023) & ~(u32)1023;
  const u32 ctrl = data + 196608;
  const u32 bfl[3] = {ctrl, ctrl + 8, ctrl + 16};
  const u32 bem[3] = {ctrl + 24, ctrl + 32, ctrl + 40};
  const u32 bdone = ctrl + 48, btm = ctrl + 56;
  const int tid = threadIdx.x, wid = tid >> 5;
  const int z = blockIdx.z;
  u32 alive = 1;
  const u16* Ap = A; const u16* Bp = B;
  float* Cf = (float*)Cv; u16* Ch = (u16*)Cv;
  if (mode == 4) {
    Ap += (long long)(z >> 9) * (512*768);
    Bp += (long long)z * (256*768);
    Cf += (long long)z * (512*256);
  } else {
    Ap += (long long)z * saz; Bp += (long long)z * sbz;
    Cf += (long long)z * scz; Ch += (long long)z * scz;
  }
  const float* b1z = b1 + (long long)z * bstr;
  const int m0 = blockIdx.y * 256, n0 = blockIdx.x * 256;
  if (tid == 0) {
    asm volatile("mbarrier.init.shared.b64 [%0], 256;"::"r"(bfl[0]):"memory");
    asm volatile("mbarrier.init.shared.b64 [%0], 256;"::"r"(bfl[1]):"memory");
    asm volatile("mbarrier.init.shared.b64 [%0], 256;"::"r"(bfl[2]):"memory");
    asm volatile("mbarrier.init.shared.b64 [%0], 1;"::"r"(bem[0]):"memory");
    asm volatile("mbarrier.init.shared.b64 [%0], 1;"::"r"(bem[1]):"memory");
    asm volatile("mbarrier.init.shared.b64 [%0], 1;"::"r"(bem[2]):"memory");
    asm volatile("mbarrier.init.shared.b64 [%0], 1;"::"r"(bdone):"memory");
  }
  if (wid == 8) {
    asm volatile("tcgen05.alloc.cta_group::1.sync.aligned.shared::cta.b32 [%0], 512;"::"r"(btm):"memory");
    asm volatile("tcgen05.relinquish_alloc_permit.cta_group::1.sync.aligned;");
  }
  __syncthreads();
  u32 tmem; asm volatile("ld.shared.b32 %0, [%1];":"=r"(tmem):"r"(btm));

  // stage layout: stage s at data + s*65536: A (256 rows x 128B = 32KB) then B (32KB)
  if (tid < 256) {
    const u16* pa[8]; const u16* pb[8]; u32 qa0[8], qb0[8];
    #pragma unroll
    for (int i = 0; i < 8; i++) {
      int f = tid + i * 256, r = f >> 3, cu = f & 7;
      pa[i] = Ap + (long long)(m0 + r) * lda + cu * 8;
      pb[i] = Bp + (long long)(n0 + r) * ldb + cu * 8;
      u32 off = (u32)(r * 128 + cu * 16); u32 sw = off ^ ((off >> 3) & 0x70);
      qa0[i] = data + sw; qb0[i] = data + 32768 + sw;
    }
    int s = 0, ph = 0;
    for (int k = 0; k < 12; k++) {
      if (k >= 3) MWAIT(bem[s], ph ^ 1);
      const u32 so = (u32)s * 65536;
      #pragma unroll
      for (int i = 0; i < 8; i++)
        asm volatile("cp.async.cg.shared.global [%0], [%1], 16;"::"r"(qa0[i] + so),"l"(pa[i] + k * 64):"memory");
      #pragma unroll
      for (int i = 0; i < 8; i++)
        asm volatile("cp.async.cg.shared.global [%0], [%1], 16;"::"r"(qb0[i] + so),"l"(pb[i] + k * 64):"memory");
      asm volatile("cp.async.mbarrier.arrive.noinc.shared::cta.b64 [%0];"::"r"(bfl[s]):"memory");
      if (++s == 3) { s = 0; ph ^= 1; }
    }
  } else if (wid == 8 && (tid & 31) == 0) {
    const u64 base = (2ULL << 61) | (1ULL << 46) | (64ULL << 32) | (1ULL << 16);
    const u64 d0 = base | ((data >> 4) & 0x3FFF);
    const u32 idesc = (1u << 4) | (32u << 17) | (8u << 24);
    int s = 0, ph = 0;
    for (int k = 0; k < 12; k++) {
      MWAIT(bfl[s], ph);
      asm volatile("fence.proxy.async.shared::cta;":::"memory");
      u64 dstage = d0 + (u64)s * 4096;   // 65536B / 16
      u64 dA0 = dstage, dA1 = dstage + 1024, dB = dstage + 2048;
      #pragma unroll
      for (int i = 0; i < 4; i++) {
        u32 en = (u32)(k | i);
        asm volatile("{\n\t.reg .pred p;\n\tsetp.ne.u32 p, %4, 0;\n\t"
          "tcgen05.mma.cta_group::1.kind::f16 [%0], %1, %2, %3, {%5,%5,%5,%5}, p;\n\t}"
          ::"r"(tmem),"l"(dA0 + 2*i),"l"(dB + 2*i),"r"(idesc),"r"(en),"r"(0u):"memory");
      }
      #pragma unroll
      for (int i = 0; i < 4; i++) {
        u32 en = (u32)(k | i);
        asm volatile("{\n\t.reg .pred p;\n\tsetp.ne.u32 p, %4, 0;\n\t"
          "tcgen05.mma.cta_group::1.kind::f16 [%0], %1, %2, %3, {%5,%5,%5,%5}, p;\n\t}"
          ::"r"(tmem + 256),"l"(dA1 + 2*i),"l"(dB + 2*i),"r"(idesc),"r"(en),"r"(0u):"memory");
      }
      asm volatile("tcgen05.commit.cta_group::1.mbarrier::arrive::one.shared::cluster.b64 [%0];"::"r"(bem[s]):"memory");
      if (++s == 3) { s = 0; ph ^= 1; }
    }
    asm volatile("tcgen05.commit.cta_group::1.mbarrier::arrive::one.shared::cluster.b64 [%0];"::"r"(bdone):"memory");
  }

  MWAIT(bdone, 0);
  asm volatile("tcgen05.fence::after_thread_sync;":::"memory");

  if (tid < 256) {
    const int grp = tid >> 7;
    const int lt = tid & 127;
    const long long row = m0 + grp * 128 + lt;
    const u32 tbase = tmem + (u32)grp * 256;
    const float* lsr = 0; const float* ler = 0;
    if (mode == 4) {
      lsr = Lsg + (long long)z * 256;
      ler = Leg + ((long long)(z >> 9) * 512 + row) * 256;
    }
    for (int nc = 0; nc < 8; nc++) {
      u32 r[32];
      asm volatile("tcgen05.ld.sync.aligned.32x32b.x32.b32 "
        "{%0,%1,%2,%3,%4,%5,%6,%7,%8,%9,%10,%11,%12,%13,%14,%15,"
        "%16,%17,%18,%19,%20,%21,%22,%23,%24,%25,%26,%27,%28,%29,%30,%31}, [%32];"
        : "=r"(r[0]),"=r"(r[1]),"=r"(r[2]),"=r"(r[3]),"=r"(r[4]),"=r"(r[5]),"=r"(r[6]),"=r"(r[7]),
          "=r"(r[8]),"=r"(r[9]),"=r"(r[10]),"=r"(r[11]),"=r"(r[12]),"=r"(r[13]),"=r"(r[14]),"=r"(r[15]),
          "=r"(r[16]),"=r"(r[17]),"=r"(r[18]),"=r"(r[19]),"=r"(r[20]),"=r"(r[21]),"=r"(r[22]),"=r"(r[23]),
          "=r"(r[24]),"=r"(r[25]),"=r"(r[26]),"=r"(r[27]),"=r"(r[28]),"=r"(r[29]),"=r"(r[30]),"=r"(r[31])
        : "r"(tbase + nc * 32));
      asm volatile("tcgen05.wait::ld.sync.aligned;":::"memory");
      const int nb = n0 + nc * 32;
      float v[32];
      #pragma unroll
      for (int c = 0; c < 32; c++) {
        float x; asm("mov.b32 %0, %1;" : "=f"(x) : "r"(r[c]));
        const int n = nb + c;
        if (mode == 1)      { x = x + b1z[n]; x = x > 0.f ? x : 0.f; }
        else if (mode == 2) x = x + b1z[n];
        else if (mode == 4) x += lsr[n] + ler[n] + W2bg[n] + biasg[n];
        v[c] = x;
      }
      if (mode == 0 || mode == 4) {
        float* dst = Cf + row * ldc + nb;
        #pragma unroll
        for (int j = 0; j < 8; j++)
          asm volatile("st.global.v4.f32 [%0], {%1,%2,%3,%4};"
            ::"l"(dst + 4*j),"f"(v[4*j]),"f"(v[4*j+1]),"f"(v[4*j+2]),"f"(v[4*j+3]):"memory");
      } else {
        u16* dst = Ch + row * ldc + nb;
        u32 hp[16];
        #pragma unroll
        for (int j = 0; j < 16; j++) {
          asm("{\n\t.reg .b16 lo, hi;\n\tcvt.rn.f16.f32 lo, %1;\n\tcvt.rn.f16.f32 hi, %2;\n\t"
              "mov.b32 %0, {lo, hi};\n\t}" : "=r"(hp[j]) : "f"(v[2*j]), "f"(v[2*j+1]));
        }
        #pragma unroll
        for (int j = 0; j < 4; j++)
          asm volatile("st.global.v4.b32 [%0], {%1,%2,%3,%4};"
            ::"l"(dst + 8*j),"r"(hp[4*j]),"r"(hp[4*j+1]),"r"(hp[4*j+2]),"r"(hp[4*j+3]):"memory");
      }
    }
  }
  __syncthreads();
  if (wid == 8)
    asm volatile("tcgen05.dealloc.cta_group::1.sync.aligned.b32 %0, 512;"::"r"(tmem));
}
)XX";

// ---------------------------------------------------------------------------
// Runtime JIT plumbing (dlopen NVRTC + libcuda; no extra link deps)
// ---------------------------------------------------------------------------
#define TC_SMEM 197760

#if defined(CUDA_API_PER_THREAD_DEFAULT_STREAM) || defined(__CUDA_API_PER_THREAD_DEFAULT_STREAM__)
#define HS ((void*)0x2)
#else
#define HS ((void*)0x1)
#endif

typedef int (*nvrtcCreate_t)(void**, const char*, const char*, int, const char* const*, const char* const*);
typedef int (*nvrtcCompile_t)(void*, int, const char* const*);
typedef int (*nvrtcGetSize_t)(void*, size_t*);
typedef int (*nvrtcGetData_t)(void*, char*);
typedef int (*cuModLoad_t)(void**, const void*);
typedef int (*cuModGetFn_t)(void**, void*, const char*);
typedef int (*cuFnSetAttr_t)(void*, int, int);
typedef int (*cuLaunch_t)(void*, unsigned, unsigned, unsigned, unsigned, unsigned, unsigned,
                          unsigned, void*, void**, void**);

static int g_init_done = 0;
static int g_use_tc = 0;
static void* g_fn = nullptr;
static cuLaunch_t p_launch = nullptr;

static int tc_gemm(int gx, int gy, int gz,
                   const void* A, long long saz, int lda,
                   const void* B, long long sbz, int ldb,
                   void* C, long long scz, long long ldc, int mode,
                   const void* b1, long long bstr,
                   const void* Ls, const void* Le,
                   const void* W2b, const void* bias)
{
    void* args[16] = {(void*)&A, (void*)&saz, (void*)&lda, (void*)&B, (void*)&sbz, (void*)&ldb,
                      (void*)&C, (void*)&scz, (void*)&ldc, (void*)&mode, (void*)&b1, (void*)&bstr,
                      (void*)&Ls, (void*)&Le, (void*)&W2b, (void*)&bias};
    return p_launch(g_fn, gx, gy, gz, 288, 1, 1, TC_SMEM, HS, args, 0);
}

static void* try_dlopen(const char* const* names, int n) {
    for (int i = 0; i < n; i++) {
        void* h = dlopen(names[i], RTLD_NOW | RTLD_GLOBAL);
        if (h) return h;
    }
    return nullptr;
}

static void init_tc(__half* Xh, __half* w13h, __half* W1th, __half* Th,
                    float* LsLe, int* badp)
{
    const char* nvrtc_names[] = {"libnvrtc.so", "libnvrtc.so.13", "libnvrtc.so.12",
                                 "/usr/local/cuda/lib64/libnvrtc.so"};
    const char* cuda_names[] = {"libcuda.so.1", "libcuda.so"};
    void* hn = try_dlopen(nvrtc_names, 4);
    void* hc = try_dlopen(cuda_names, 2);
    if (!hn || !hc) { fprintf(stderr, "tcjit: dlopen failed nv=%p cu=%p\n", hn, hc); return; }

    auto nCreate = (nvrtcCreate_t)dlsym(hn, "nvrtcCreateProgram");
    auto nCompile = (nvrtcCompile_t)dlsym(hn, "nvrtcCompileProgram");
    auto nCubSz = (nvrtcGetSize_t)dlsym(hn, "nvrtcGetCUBINSize");
    auto nCub = (nvrtcGetData_t)dlsym(hn, "nvrtcGetCUBIN");
    auto nLogSz = (nvrtcGetSize_t)dlsym(hn, "nvrtcGetProgramLogSize");
    auto nLog = (nvrtcGetData_t)dlsym(hn, "nvrtcGetProgramLog");
    auto mLoad = (cuModLoad_t)dlsym(hc, "cuModuleLoadData");
    auto mGetFn = (cuModGetFn_t)dlsym(hc, "cuModuleGetFunction");
    auto fAttr = (cuFnSetAttr_t)dlsym(hc, "cuFuncSetAttribute");
    p_launch = (cuLaunch_t)dlsym(hc, "cuLaunchKernel");
    if (!nCreate || !nCompile || !nCubSz || !nCub || !mLoad || !mGetFn || !fAttr || !p_launch) {
        fprintf(stderr, "tcjit: dlsym failed\n"); return;
    }

    void* prog = nullptr;
    if (nCreate(&prog, TC_SRC, "tc.cu", 0, nullptr, nullptr)) {
        fprintf(stderr, "tcjit: create failed\n"); return;
    }
    const char* opts1[] = {"--gpu-architecture=sm_103a", "--std=c++14"};
    int cres = nCompile(prog, 2, opts1);
    if (cres) {
        if (nLogSz && nLog) {
            size_t ls = 0; nLogSz(prog, &ls);
            if (ls > 1) { char* lg = (char*)malloc(ls + 1); nLog(prog, lg); lg[ls] = 0;
                          fprintf(stderr, "tcjit: compile log:\n%s\n", lg); free(lg); }
        }
        fprintf(stderr, "tcjit: sm_103a compile failed (%d)\n", cres);
        return;
    }
    size_t csz = 0;
    if (nCubSz(prog, &csz) || csz == 0) { fprintf(stderr, "tcjit: cubin size fail\n"); return; }
    char* cub = (char*)malloc(csz);
    nCub(prog, cub);
    void* mod = nullptr;
    int lr = mLoad(&mod, cub);
    free(cub);
    if (lr) { fprintf(stderr, "tcjit: module load failed %d\n", lr); return; }
    if (mGetFn(&g_fn, mod, "gtc")) { fprintf(stderr, "tcjit: getfn failed\n"); return; }
    fAttr(g_fn, 8 /*CU_FUNC_ATTRIBUTE_MAX_DYNAMIC_SHARED_SIZE_BYTES*/, TC_SMEM);

    // ---- validation + diagnostic ----
    fillh_k<<<192, 256>>>(Xh, BLD, 1u);
    fillh_k<<<192, 256>>>(w13h, HD, 7u);
    // reference (legacy) into LsLe[0:256*Cc)
    gemm_h<<<dim3(2, 2, 1), 256, SMEM_BYTES>>>(Xh, 0, Dd, w13h, 0, Dd, (void*)LsLe, 0, Cc,
                                               0, nullptr, nullptr, nullptr, nullptr, nullptr);
    // DIAGNOSTIC: full phase-A-shaped launch (W1th is zero-init scratch at this
    // point). This occupies the ncu capture slot so the profile shows the REAL
    // GEMM pipeline instead of the tiny validation launch.
    int dres = tc_gemm(3, 4, Cc, Xh, 0, Dd, W1th, (long long)HD, Dd,
                       Th, Dd, (long long)Cc * Dd, 3, 0, 0, 0, 0, 0, 0);
    if (dres) { fprintf(stderr, "tcjit: diag launch failed %d\n", dres); return; }
    // validation tc launch into LsLe[BLC:)
    int lres = tc_gemm(1, 1, 1, Xh, 0, Dd, w13h, 0, Dd, LsLe + BLC, 0, Cc,
                       0, 0, 0, 0, 0, 0, 0);
    if (lres) { fprintf(stderr, "tcjit: launch failed %d\n", lres); return; }
    cudaMemset(badp, 0, sizeof(int));
    cmp_k<<<256, 256>>>(LsLe, LsLe + BLC, 256 * Cc, badp);
    cudaError_t serr = cudaDeviceSynchronize();
    if (serr != cudaSuccess) {
        fprintf(stderr, "tcjit: validation sync error: %s\n", cudaGetErrorString(serr));
        return;
    }
    int bad = 1 << 30;
    cudaMemcpy(&bad, badp, sizeof(int), cudaMemcpyDeviceToHost);
    fprintf(stderr, "tcjit: validation mismatches = %d / %d\n", bad, 256 * Cc);
    if (bad == 0) g_use_tc = 1;
}

extern "C" void kernel_launch(void* const* d_in, const int* in_sizes, int n_in,
                              void* d_out, int out_size)
{
    const float* hidden = (const float*)d_in[0];
    const float* sw1 = (const float*)d_in[1];
    const float* sb1 = (const float*)d_in[2];
    const float* sw2 = (const float*)d_in[3];
    const float* sb2 = (const float*)d_in[4];
    const float* ew1 = (const float*)d_in[5];
    const float* eb1 = (const float*)d_in[6];
    const float* ew2 = (const float*)d_in[7];
    const float* eb2 = (const float*)d_in[8];
    const float* W1  = (const float*)d_in[9];
    const float* W2w = (const float*)d_in[10];
    const float* W2b = (const float*)d_in[11];
    const float* bs  = (const float*)d_in[12];
    float* out = (float*)d_out;

    __half *Xh, *w13h, *w24h, *W2h, *W1th, *Htmp2, *HsHe, *Th;
    float *LsLe, *b1x, *b2x;
    int* badp;
    cudaGetSymbolAddress((void**)&Xh, g_Xh);
    cudaGetSymbolAddress((void**)&w13h, g_w13h);
    cudaGetSymbolAddress((void**)&w24h, g_w24h);
    cudaGetSymbolAddress((void**)&W2h, g_W2h);
    cudaGetSymbolAddress((void**)&W1th, g_W1th);
    cudaGetSymbolAddress((void**)&Htmp2, g_Htmp2);
    cudaGetSymbolAddress((void**)&HsHe, g_HsHe);
    cudaGetSymbolAddress((void**)&Th, g_Th);
    cudaGetSymbolAddress((void**)&LsLe, g_LsLe);
    cudaGetSymbolAddress((void**)&b1x, g_b1x);
    cudaGetSymbolAddress((void**)&b2x, g_b2x);
    cudaGetSymbolAddress((void**)&badp, g_bad);

    if (!g_init_done) {
        cudaFuncSetAttribute(gemm_h, cudaFuncAttributeMaxDynamicSharedMemorySize, SMEM_BYTES);
        init_tc(Xh, w13h, W1th, Th, LsLe, badp);
        g_init_done = 1;
    }

    // fused prep: all f32->f16 conversions in one launch + bias gather + W1 transpose
    f2h_multi<<<512, 256>>>(hidden, sw1, ew1, sw2, ew2, W2w, Xh, w13h, w24h, W2h);
    biascpy<<<3, 256>>>(sb1, eb1, sb2, eb2, b1x, b2x);
    transpose_h<<<dim3(24, 24, Cc), dim3(32, 8)>>>(W1, W1th);

    int tc_ok = 0;
    if (g_use_tc) {
        // MLP layer 1, s+e batched via z: grid (3,4,2)
        tc_ok = (tc_gemm(3, 4, 2, Xh, 0, Dd, w13h, HD, Dd, Htmp2, BLD, Dd,
                         1, b1x, Dd, 0, 0, 0, 0) == 0);
        if (!tc_ok) g_use_tc = 0;
    }
    if (tc_ok) {
        // MLP layer 2, s+e batched
        tc_gemm(3, 4, 2, Htmp2, BLD, Dd, w24h, HD, Dd, HsHe, BLD, Dd,
                2, b2x, Dd, 0, 0, 0, 0);
        // Ls/Le batched: B offset per z = 768 within W2h rows (ldb = 1536)
        tc_gemm(1, 4, 2, HsHe, BLD, Dd, W2h, Dd, 2 * Dd, LsLe, (long long)BLC, Cc,
                0, 0, 0, 0, 0, 0, 0);
        // Phase A: T[bi,c,e] = sum_d Hs[bi,d] * W1th[c,e,d]   (z = c)
        tc_gemm(3, 4, Cc, HsHe, 0, Dd, W1th, (long long)HD, Dd,
                Th, Dd, (long long)Cc * Dd, 3, 0, 0, 0, 0, 0, 0);
        // Phase B: z = bi
        tc_gemm(1, 2, BLn, HsHe + BLD, 0, Dd, Th, 0, Dd, out, 0, Cc,
                4, 0, 0, LsLe, LsLe + BLC, W2b, bs);
    } else {
        const dim3 blk(256);
        gemm_h<<<dim3(6, 8, 1), blk, SMEM_BYTES>>>(Xh, 0, Dd, w13h, 0, Dd, Htmp2, 0, Dd,
                                                   1, sb1, nullptr, nullptr, nullptr, nullptr);
        gemm_h<<<dim3(6, 8, 1), blk, SMEM_BYTES>>>(Htmp2, 0, Dd, w24h, 0, Dd, HsHe, 0, Dd,
                                                   2, sb2, nullptr, nullptr, nullptr, nullptr);
        gemm_h<<<dim3(6, 8, 1), blk, SMEM_BYTES>>>(Xh, 0, Dd, w13h + HD, 0, Dd, Htmp2 + BLD, 0, Dd,
                                                   1, eb1, nullptr, nullptr, nullptr, nullptr);
        gemm_h<<<dim3(6, 8, 1), blk, SMEM_BYTES>>>(Htmp2 + BLD, 0, Dd, w24h + HD, 0, Dd, HsHe + BLD, 0, Dd,
                                                   2, eb2, nullptr, nullptr, nullptr, nullptr);
        gemm_h<<<dim3(2, 8, 1), blk, SMEM_BYTES>>>(HsHe, 0, Dd, W2h, 0, 2 * Dd, LsLe, 0, Cc,
                                                   0, nullptr, nullptr, nullptr, nullptr, nullptr);
        gemm_h<<<dim3(2, 8, 1), blk, SMEM_BYTES>>>(HsHe + BLD, 0, Dd, W2h + Dd, 0, 2 * Dd, LsLe + BLC, 0, Cc,
                                                   0, nullptr, nullptr, nullptr, nullptr, nullptr);
        gemm_h<<<dim3(6, 8, Cc), blk, SMEM_BYTES>>>(HsHe, 0, Dd,
                                                    W1th, (long)HD, Dd,
                                                    Th, (long)Dd, (long)Cc * Dd,
                                                    3, nullptr, nullptr, nullptr, nullptr, nullptr);
        gemm_h<<<dim3(2, 4, BLn), blk, SMEM_BYTES>>>(HsHe + BLD, 0, Dd, Th, 0, Dd, out, 0, Cc,
                                                     4, nullptr, LsLe, LsLe + BLC, W2b, bs);
    }
}